// round 4
// baseline (speedup 1.0000x reference)
#include <cuda_runtime.h>
#include <cuda_bf16.h>
#include <math.h>

#define NN 100000
#define DD 256
#define EE 320000
#define GG 4096
#define LLAYERS 3
#define OUTW 1280          // (L+2)*D
#define EPS 1e-5f

// ---------------- scratch (device globals; no allocation) ----------------
// layout (floats):
//  h   : 0
//  agg : 1*N*D
//  t1  : 2*N*D
//  g   : 3*N*D
//  m   : 4*N*D
//  e   : 5*N*D
//  gi  : 6*N*D   (3*N*D)
//  gh  : 9*N*D   (3*N*D)
__device__ float g_scratch[12ULL * NN * DD];

__device__ float g_bnsum[DD];
__device__ float g_bnsq[DD];
__device__ float g_scale[DD];
__device__ float g_shift[DD];
__device__ int   g_segs[GG];
__device__ int   g_sege[GG];

// ---------------- small utility kernels ----------------
__global__ void vcopy4(const float4* __restrict__ src, float4* __restrict__ dst, int n4) {
    int i = blockIdx.x * blockDim.x + threadIdx.x;
    if (i < n4) dst[i] = src[i];
}

__global__ void seg_init_kernel() {
    int g = blockIdx.x * blockDim.x + threadIdx.x;
    if (g < GG) { g_segs[g] = 0; g_sege[g] = 0; }
}

__global__ void seg_bounds_kernel(const int* __restrict__ batch) {
    int i = blockIdx.x * blockDim.x + threadIdx.x;
    if (i >= NN) return;
    int b = batch[i];
    if (i == 0 || batch[i - 1] != b) g_segs[b] = i;
    if (i == NN - 1 || batch[i + 1] != b) g_sege[b] = i + 1;
}

__global__ void bn_zero_kernel() {
    int c = threadIdx.x;
    if (c < DD) { g_bnsum[c] = 0.f; g_bnsq[c] = 0.f; }
}

// column-wise sums over g (for BatchNorm): block = 256 threads (one per col),
// each block covers a 256-row chunk; partials merged with atomicAdd.
__global__ void bn_stats_kernel(const float* __restrict__ gbuf) {
    int c = threadIdx.x;
    int r0 = blockIdx.x * 256;
    int r1 = min(r0 + 256, NN);
    float s = 0.f, s2 = 0.f;
    for (int r = r0; r < r1; r++) {
        float v = gbuf[(size_t)r * DD + c];
        s += v;
        s2 += v * v;
    }
    atomicAdd(&g_bnsum[c], s);
    atomicAdd(&g_bnsq[c], s2);
}

__global__ void bn_final_kernel(const float* __restrict__ bng, const float* __restrict__ bnb) {
    int c = threadIdx.x;
    if (c >= DD) return;
    float invN = 1.f / (float)NN;
    float mean = g_bnsum[c] * invN;
    float ex2  = g_bnsq[c] * invN;
    float var  = ex2 - mean * mean;
    float sc   = bng[c] * rsqrtf(var + EPS);
    g_scale[c] = sc;
    g_shift[c] = bnb[c] - mean * sc;
}

// one block per edge: agg[dst] += h[src]
__global__ void edge_agg_kernel(const float* __restrict__ h,
                                const int* __restrict__ src,
                                const int* __restrict__ dst,
                                float* __restrict__ agg) {
    int eid = blockIdx.x;
    int s = __ldg(&src[eid]);
    int d = __ldg(&dst[eid]);
    int c = threadIdx.x;
    atomicAdd(&agg[(size_t)d * DD + c], __ldg(&h[(size_t)s * DD + c]));
}

// ---------------- tiled fp32 GEMM:  C[M,O] = A[M,256] @ W[O,256]^T + bias ----------------
// BM=128, BN=64, BK=16, 256 threads, 8x4 microtile per thread.
// doAffine: A element a[.,k] -> a*g_scale[k] + g_shift[k]  (BatchNorm fold)
__global__ __launch_bounds__(256) void gemm_kernel(
    const float* __restrict__ A, const float* __restrict__ W,
    const float* __restrict__ bias, float* __restrict__ C,
    int M, int O, int doRelu, int doAffine)
{
    __shared__ float As[16][132];   // [k][m], padded
    __shared__ float Bs[16][68];    // [k][n], padded

    int tid = threadIdx.x;
    int tx = tid & 15;   // N dir (0..15) -> 4 cols each
    int ty = tid >> 4;   // M dir (0..15) -> 8 rows each
    int rowBase = blockIdx.y * 128;
    int colBase = blockIdx.x * 64;

    float acc[8][4];
#pragma unroll
    for (int i = 0; i < 8; i++)
#pragma unroll
        for (int j = 0; j < 4; j++) acc[i][j] = 0.f;

    for (int kt = 0; kt < DD; kt += 16) {
        // ---- load A tile: 128x16 = 512 float4 -> 2 per thread ----
#pragma unroll
        for (int l = 0; l < 2; l++) {
            int q = tid + l * 256;
            int row = q >> 2;
            int kq = q & 3;
            int grow = rowBase + row;
            float4 v = make_float4(0.f, 0.f, 0.f, 0.f);
            if (grow < M)
                v = *(const float4*)(A + (size_t)grow * DD + kt + kq * 4);
            if (doAffine) {
                int kk = kt + kq * 4;
                v.x = fmaf(v.x, g_scale[kk + 0], g_shift[kk + 0]);
                v.y = fmaf(v.y, g_scale[kk + 1], g_shift[kk + 1]);
                v.z = fmaf(v.z, g_scale[kk + 2], g_shift[kk + 2]);
                v.w = fmaf(v.w, g_scale[kk + 3], g_shift[kk + 3]);
            }
            As[kq * 4 + 0][row] = v.x;
            As[kq * 4 + 1][row] = v.y;
            As[kq * 4 + 2][row] = v.z;
            As[kq * 4 + 3][row] = v.w;
        }
        // ---- load B tile: 64x16 = 256 float4 -> 1 per thread ----
        {
            int o = tid >> 2;
            int kq = tid & 3;
            float4 v = *(const float4*)(W + (size_t)(colBase + o) * DD + kt + kq * 4);
            Bs[kq * 4 + 0][o] = v.x;
            Bs[kq * 4 + 1][o] = v.y;
            Bs[kq * 4 + 2][o] = v.z;
            Bs[kq * 4 + 3][o] = v.w;
        }
        __syncthreads();

#pragma unroll
        for (int k = 0; k < 16; k++) {
            float4 a0 = *(const float4*)&As[k][ty * 8];
            float4 a1 = *(const float4*)&As[k][ty * 8 + 4];
            float4 b0 = *(const float4*)&Bs[k][tx * 4];
            float av[8] = {a0.x, a0.y, a0.z, a0.w, a1.x, a1.y, a1.z, a1.w};
            float bv[4] = {b0.x, b0.y, b0.z, b0.w};
#pragma unroll
            for (int i = 0; i < 8; i++)
#pragma unroll
                for (int j = 0; j < 4; j++)
                    acc[i][j] = fmaf(av[i], bv[j], acc[i][j]);
        }
        __syncthreads();
    }

    // ---- epilogue: +bias, optional relu, float4 store ----
    int gcol = colBase + tx * 4;
    float b0 = bias[gcol + 0], b1 = bias[gcol + 1], b2 = bias[gcol + 2], b3 = bias[gcol + 3];
#pragma unroll
    for (int i = 0; i < 8; i++) {
        int grow = rowBase + ty * 8 + i;
        if (grow >= M) continue;
        float4 v;
        v.x = acc[i][0] + b0;
        v.y = acc[i][1] + b1;
        v.z = acc[i][2] + b2;
        v.w = acc[i][3] + b3;
        if (doRelu) {
            v.x = fmaxf(v.x, 0.f); v.y = fmaxf(v.y, 0.f);
            v.z = fmaxf(v.z, 0.f); v.w = fmaxf(v.w, 0.f);
        }
        *(float4*)(C + (size_t)grow * O + gcol) = v;
    }
}

// ---------------- GRU gates + LayerNorm + m/e update (one block per node) ----------------
__inline__ __device__ float warpsum(float v) {
#pragma unroll
    for (int o = 16; o > 0; o >>= 1) v += __shfl_xor_sync(0xffffffffu, v, o);
    return v;
}

__global__ __launch_bounds__(256) void gru_ln_kernel(
    const float* __restrict__ gi, const float* __restrict__ gh,
    float* __restrict__ h, const float* __restrict__ lng, const float* __restrict__ lnb,
    float* __restrict__ m, float* __restrict__ e, int first)
{
    int n = blockIdx.x;
    int c = threadIdx.x;
    const float* gin = gi + (size_t)n * 768;
    const float* ghn = gh + (size_t)n * 768;

    float ir = gin[c],       iz = gin[256 + c], inn = gin[512 + c];
    float hr = ghn[c],       hz = ghn[256 + c], hnn = ghn[512 + c];
    float r  = 1.f / (1.f + expf(-(ir + hr)));
    float z  = 1.f / (1.f + expf(-(iz + hz)));
    float nn = tanhf(inn + r * hnn);
    float hold = h[(size_t)n * DD + c];
    float hv = (1.f - z) * nn + z * hold;

    // LayerNorm over the 256 features of this node
    __shared__ float sbuf[8];
    int lane = c & 31, w = c >> 5;
    float s = warpsum(hv);
    if (lane == 0) sbuf[w] = s;
    __syncthreads();
    float mu = 0.f;
#pragma unroll
    for (int i = 0; i < 8; i++) mu += sbuf[i];
    mu *= (1.f / 256.f);
    __syncthreads();
    float d0 = hv - mu;
    float s2 = warpsum(d0 * d0);
    if (lane == 0) sbuf[w] = s2;
    __syncthreads();
    float var = 0.f;
#pragma unroll
    for (int i = 0; i < 8; i++) var += sbuf[i];
    var *= (1.f / 256.f);

    float o = d0 * rsqrtf(var + EPS) * lng[c] + lnb[c];

    size_t idx = (size_t)n * DD + c;
    h[idx] = o;
    if (first) { m[idx] = o; e[idx] = o; }
    else       { m[idx] *= o; e[idx] += o; }
}

// ---------------- contiguous segment max (batch is sorted) ----------------
__global__ void segmax_kernel(const float* __restrict__ v, float* __restrict__ out, int slot) {
    int g = blockIdx.x;
    int c = threadIdx.x;
    int s = g_segs[g], t = g_sege[g];
    float mx = -INFINITY;
    for (int n = s; n < t; n++)
        mx = fmaxf(mx, v[(size_t)n * DD + c]);
    out[(size_t)g * OUTW + slot * DD + c] = mx;
}

// ---------------- launch ----------------
extern "C" void kernel_launch(void* const* d_in, const int* in_sizes, int n_in,
                              void* d_out, int out_size) {
    const float* x       = (const float*)d_in[0];
    const float* lin1_w  = (const float*)d_in[1];
    const float* lin1_b  = (const float*)d_in[2];
    const float* lin2_w  = (const float*)d_in[3];
    const float* lin2_b  = (const float*)d_in[4];
    const float* bn_g    = (const float*)d_in[5];
    const float* bn_b    = (const float*)d_in[6];
    const float* gru_wih = (const float*)d_in[7];
    const float* gru_whh = (const float*)d_in[8];
    const float* gru_bih = (const float*)d_in[9];
    const float* gru_bhh = (const float*)d_in[10];
    const float* ln_g    = (const float*)d_in[11];
    const float* ln_b    = (const float*)d_in[12];
    const int*   edges   = (const int*)d_in[13];   // [2,E]: src then dst
    const int*   batch   = (const int*)d_in[14];
    float* out = (float*)d_out;

    float* S = nullptr;
    cudaGetSymbolAddress((void**)&S, g_scratch);
    const size_t ND = (size_t)NN * DD;
    float* bh   = S;
    float* bagg = S + 1 * ND;
    float* bt1  = S + 2 * ND;
    float* bg   = S + 3 * ND;
    float* bm   = S + 4 * ND;
    float* be   = S + 5 * ND;
    float* bgi  = S + 6 * ND;
    float* bgh  = S + 9 * ND;

    const int n4 = (int)(ND / 4);
    const int CP_BLOCKS = (n4 + 255) / 256;
    const dim3 gemm_grid_d(DD / 64, (NN + 127) / 128);
    const dim3 gemm_grid_3d(3 * DD / 64, (NN + 127) / 128);

    // h = x ; segment bounds
    vcopy4<<<CP_BLOCKS, 256>>>((const float4*)x, (float4*)bh, n4);
    seg_init_kernel<<<(GG + 255) / 256, 256>>>();
    seg_bounds_kernel<<<(NN + 255) / 256, 256>>>(batch);

    for (int i = 0; i < LLAYERS; i++) {
        // agg = h + scatter-add of neighbor features
        vcopy4<<<CP_BLOCKS, 256>>>((const float4*)bh, (float4*)bagg, n4);
        edge_agg_kernel<<<EE, 256>>>(bh, edges, edges + EE, bagg);

        // GIN MLP: t1 = relu(agg @ W1^T + b1); g = relu(t1 @ W2^T + b2)
        gemm_kernel<<<gemm_grid_d, 256>>>(bagg, lin1_w + (size_t)i * DD * DD,
                                          lin1_b + (size_t)i * DD, bt1, NN, DD, 1, 0);
        gemm_kernel<<<gemm_grid_d, 256>>>(bt1, lin2_w + (size_t)i * DD * DD,
                                          lin2_b + (size_t)i * DD, bg, NN, DD, 1, 0);

        // BatchNorm stats -> per-feature affine (folded into gi GEMM)
        bn_zero_kernel<<<1, 256>>>();
        bn_stats_kernel<<<(NN + 255) / 256, 256>>>(bg);
        bn_final_kernel<<<1, 256>>>(bn_g + (size_t)i * DD, bn_b + (size_t)i * DD);

        // GRU matmuls: gi = bn(g) @ Wih^T + bih ; gh = h @ Whh^T + bhh
        gemm_kernel<<<gemm_grid_3d, 256>>>(bg, gru_wih + (size_t)i * 3 * DD * DD,
                                           gru_bih + (size_t)i * 3 * DD, bgi, NN, 3 * DD, 0, 1);
        gemm_kernel<<<gemm_grid_3d, 256>>>(bh, gru_whh + (size_t)i * 3 * DD * DD,
                                           gru_bhh + (size_t)i * 3 * DD, bgh, NN, 3 * DD, 0, 0);

        // gates + LayerNorm + m/e, writes h in place
        gru_ln_kernel<<<NN, 256>>>(bgi, bgh, bh, ln_g, ln_b, bm, be, i == 0);

        // out[:, i*D:(i+1)*D] = segment_max(h)
        segmax_kernel<<<GG, 256>>>(bh, out, i);
    }

    segmax_kernel<<<GG, 256>>>(bm, out, 3);
    segmax_kernel<<<GG, 256>>>(be, out, 4);
}

// round 6
// speedup vs baseline: 1.6771x; 1.6771x over previous
#include <cuda_runtime.h>
#include <cuda_bf16.h>
#include <cstdint>
#include <math.h>

#define NN 100000
#define DD 256
#define EE 320000
#define GG 4096
#define LLAYERS 3
#define OUTW 1280
#define EPS 1e-5f

// ---------------- scratch (device globals; no allocation) ----------------
__device__ float g_scratch[12ULL * NN * DD];
__device__ float g_bnsum[DD];
__device__ float g_bnsq[DD];
__device__ float g_scale[DD];
__device__ float g_shift[DD];
__device__ int   g_segs[GG];
__device__ int   g_sege[GG];

// ---------------- helpers ----------------
__device__ __forceinline__ uint32_t smem_u32(const void* p) {
    uint32_t a;
    asm("{ .reg .u64 t; cvta.to.shared.u64 t, %1; cvt.u32.u64 %0, t; }" : "=r"(a) : "l"(p));
    return a;
}
__device__ __forceinline__ uint32_t tf32r(float f) {
    uint32_t u;
    asm("cvt.rna.tf32.f32 %0, %1;" : "=r"(u) : "f"(f));
    return u;
}
__device__ __forceinline__ void ldm_x4(uint32_t& r0, uint32_t& r1, uint32_t& r2, uint32_t& r3,
                                       uint32_t addr) {
    asm volatile("ldmatrix.sync.aligned.m8n8.x4.shared.b16 {%0,%1,%2,%3}, [%4];"
                 : "=r"(r0), "=r"(r1), "=r"(r2), "=r"(r3) : "r"(addr));
}
__device__ __forceinline__ void mma_tf32(float* d, const uint32_t* a, const uint32_t* b) {
    asm volatile("mma.sync.aligned.m16n8k8.row.col.f32.tf32.tf32.f32 "
                 "{%0,%1,%2,%3}, {%4,%5,%6,%7}, {%8,%9}, {%0,%1,%2,%3};"
                 : "+f"(d[0]), "+f"(d[1]), "+f"(d[2]), "+f"(d[3])
                 : "r"(a[0]), "r"(a[1]), "r"(a[2]), "r"(a[3]), "r"(b[0]), "r"(b[1]));
}

// SMEM layout (floats, pitch 36 per 32-wide row chunk):
//  A buf: 128 rows * 36  -> 18432 B;  two bufs.  B same, offset 36864.
#define PITCHF 36
#define PITCHB 144
#define BUFSZ 18432
#define SMEM_DYN 73728

// ---------------- tf32 mma.sync GEMM: C[M,O] = A[M,256] @ W[O,256]^T + bias ----------------
// CTA tile 128x128, 256 thr (8 warps = 4M x 2N, warp tile 32x64), K chunk 32, dbl-buffered.
__global__ __launch_bounds__(256) void gemm_mma(
    const float* __restrict__ A, const float* __restrict__ W,
    const float* __restrict__ bias, float* __restrict__ C,
    int M, int O, int doRelu)
{
    extern __shared__ float smem[];
    const uint32_t sb = smem_u32(smem);
    const int tid = threadIdx.x, lane = tid & 31, wid = tid >> 5;
    const int rowBase = blockIdx.y * 128, colBase = blockIdx.x * 128;
    const int wm = (wid & 3) * 32;        // warp M offset in tile
    const int wn = (wid >> 2) * 64;       // warp N offset in tile

    // staging: thread t loads row (t>>1), 16-float half (t&1)
    const int srow = tid >> 1;
    const int shalf = (tid & 1) * 16;
    const float* Asrc = A + (size_t)min(rowBase + srow, M - 1) * DD + shalf;
    const float* Bsrc = W + (size_t)(colBase + srow) * DD + shalf;
    char* sA = (char*)smem;               // A bufs at [0, 2*BUFSZ)
    char* sB = (char*)smem + 2 * BUFSZ;   // B bufs
    const int stsOff = (srow * PITCHF + shalf) * 4;

    // ldmatrix per-lane base addresses (within a buffer)
    const int aRow = wm + (lane & 7) + ((lane >> 3) & 1) * 8;
    const int aColB = ((lane >> 4) * 4) * 4;
    const uint32_t aBase = sb + aRow * PITCHB + aColB;
    const int bRow = wn + (lane & 7) + (lane >> 4) * 8;
    const int bColB = (((lane >> 3) & 1) * 4) * 4;
    const uint32_t bBase = sb + 2 * BUFSZ + bRow * PITCHB + bColB;

    float4 ra[4], rb[4];
#pragma unroll
    for (int j = 0; j < 4; j++) {
        ra[j] = *(const float4*)(Asrc + j * 4);
        rb[j] = *(const float4*)(Bsrc + j * 4);
    }

    float acc[2][8][4];
#pragma unroll
    for (int mt = 0; mt < 2; mt++)
#pragma unroll
        for (int nt = 0; nt < 8; nt++)
#pragma unroll
            for (int q = 0; q < 4; q++) acc[mt][nt][q] = 0.f;

#pragma unroll 1
    for (int c = 0; c < 8; c++) {
        const int buf = c & 1;
        // ---- stage chunk c (cvt.rna to tf32 bits) ----
        char* dstA = sA + buf * BUFSZ + stsOff;
        char* dstB = sB + buf * BUFSZ + stsOff;
#pragma unroll
        for (int j = 0; j < 4; j++) {
            uint4 ua = { tf32r(ra[j].x), tf32r(ra[j].y), tf32r(ra[j].z), tf32r(ra[j].w) };
            uint4 ub = { tf32r(rb[j].x), tf32r(rb[j].y), tf32r(rb[j].z), tf32r(rb[j].w) };
            *(uint4*)(dstA + j * 16) = ua;
            *(uint4*)(dstB + j * 16) = ub;
        }
        __syncthreads();

        // ---- prefetch chunk c+1 ----
        if (c < 7) {
            const float* An = Asrc + (c + 1) * 32;
            const float* Bn = Bsrc + (c + 1) * 32;
#pragma unroll
            for (int j = 0; j < 4; j++) {
                ra[j] = *(const float4*)(An + j * 4);
                rb[j] = *(const float4*)(Bn + j * 4);
            }
        }

        // ---- compute 4 k-steps of 8 ----
        const uint32_t aB = aBase + buf * BUFSZ;
        const uint32_t bB = bBase + buf * BUFSZ;
#pragma unroll
        for (int ks = 0; ks < 4; ks++) {
            const uint32_t kOff = ks * 8 * 4;   // kk*4 bytes
            uint32_t af[2][4];
            ldm_x4(af[0][0], af[0][1], af[0][2], af[0][3], aB + kOff);
            ldm_x4(af[1][0], af[1][1], af[1][2], af[1][3], aB + 16 * PITCHB + kOff);
            uint32_t bf[8][2];
#pragma unroll
            for (int p = 0; p < 4; p++) {
                uint32_t r0, r1, r2, r3;
                ldm_x4(r0, r1, r2, r3, bB + p * 16 * PITCHB + kOff);
                bf[2 * p][0] = r0; bf[2 * p][1] = r1;
                bf[2 * p + 1][0] = r2; bf[2 * p + 1][1] = r3;
            }
#pragma unroll
            for (int mt = 0; mt < 2; mt++)
#pragma unroll
                for (int nt = 0; nt < 8; nt++)
                    mma_tf32(acc[mt][nt], af[mt], bf[nt]);
        }
    }

    // ---- epilogue: bias + optional relu, float2 stores ----
    const int g = lane >> 2, tig = lane & 3;
#pragma unroll
    for (int mt = 0; mt < 2; mt++) {
#pragma unroll
        for (int nt = 0; nt < 8; nt++) {
            int col = colBase + wn + nt * 8 + tig * 2;
            float2 bb = *(const float2*)(bias + col);
            int r0 = rowBase + wm + mt * 16 + g;
            int r1 = r0 + 8;
            float2 v0 = { acc[mt][nt][0] + bb.x, acc[mt][nt][1] + bb.y };
            float2 v1 = { acc[mt][nt][2] + bb.x, acc[mt][nt][3] + bb.y };
            if (doRelu) {
                v0.x = fmaxf(v0.x, 0.f); v0.y = fmaxf(v0.y, 0.f);
                v1.x = fmaxf(v1.x, 0.f); v1.y = fmaxf(v1.y, 0.f);
            }
            if (r0 < M) *(float2*)(C + (size_t)r0 * O + col) = v0;
            if (r1 < M) *(float2*)(C + (size_t)r1 * O + col) = v1;
        }
    }
}

// ---------------- small utility kernels ----------------
__global__ void vcopy4(const float4* __restrict__ src, float4* __restrict__ dst, int n4) {
    int i = blockIdx.x * blockDim.x + threadIdx.x;
    if (i < n4) dst[i] = src[i];
}

__global__ void seg_init_kernel() {
    int g = blockIdx.x * blockDim.x + threadIdx.x;
    if (g < GG) { g_segs[g] = 0; g_sege[g] = 0; }
}

__global__ void seg_bounds_kernel(const int* __restrict__ batch) {
    int i = blockIdx.x * blockDim.x + threadIdx.x;
    if (i >= NN) return;
    int b = batch[i];
    if (i == 0 || batch[i - 1] != b) g_segs[b] = i;
    if (i == NN - 1 || batch[i + 1] != b) g_sege[b] = i + 1;
}

__global__ void bn_zero_kernel() {
    int c = threadIdx.x;
    if (c < DD) { g_bnsum[c] = 0.f; g_bnsq[c] = 0.f; }
}

__global__ void bn_stats_kernel(const float* __restrict__ gbuf) {
    int c = threadIdx.x;
    int r0 = blockIdx.x * 256;
    int r1 = min(r0 + 256, NN);
    float s = 0.f, s2 = 0.f;
    for (int r = r0; r < r1; r++) {
        float v = gbuf[(size_t)r * DD + c];
        s += v; s2 += v * v;
    }
    atomicAdd(&g_bnsum[c], s);
    atomicAdd(&g_bnsq[c], s2);
}

__global__ void bn_final_kernel(const float* __restrict__ bng, const float* __restrict__ bnb) {
    int c = threadIdx.x;
    if (c >= DD) return;
    float invN = 1.f / (float)NN;
    float mean = g_bnsum[c] * invN;
    float var  = g_bnsq[c] * invN - mean * mean;
    float sc   = bng[c] * rsqrtf(var + EPS);
    g_scale[c] = sc;
    g_shift[c] = bnb[c] - mean * sc;
}

// in-place BN affine: g = g*scale + shift
__global__ void bn_apply_kernel(float* __restrict__ gbuf) {
    int c = threadIdx.x;
    size_t idx = (size_t)blockIdx.x * DD + c;
    gbuf[idx] = fmaf(gbuf[idx], g_scale[c], g_shift[c]);
}

__global__ void edge_agg_kernel(const float* __restrict__ h,
                                const int* __restrict__ src,
                                const int* __restrict__ dst,
                                float* __restrict__ agg) {
    int eid = blockIdx.x;
    int s = __ldg(&src[eid]);
    int d = __ldg(&dst[eid]);
    int c = threadIdx.x;
    atomicAdd(&agg[(size_t)d * DD + c], __ldg(&h[(size_t)s * DD + c]));
}

// ---------------- GRU gates + LayerNorm + m/e update ----------------
__inline__ __device__ float warpsum(float v) {
#pragma unroll
    for (int o = 16; o > 0; o >>= 1) v += __shfl_xor_sync(0xffffffffu, v, o);
    return v;
}

__global__ __launch_bounds__(256) void gru_ln_kernel(
    const float* __restrict__ gi, const float* __restrict__ gh,
    float* __restrict__ h, const float* __restrict__ lng, const float* __restrict__ lnb,
    float* __restrict__ m, float* __restrict__ e, int first)
{
    int n = blockIdx.x;
    int c = threadIdx.x;
    const float* gin = gi + (size_t)n * 768;
    const float* ghn = gh + (size_t)n * 768;

    float ir = gin[c], iz = gin[256 + c], inn = gin[512 + c];
    float hr = ghn[c], hz = ghn[256 + c], hnn = ghn[512 + c];
    float r  = 1.f / (1.f + expf(-(ir + hr)));
    float z  = 1.f / (1.f + expf(-(iz + hz)));
    float nn = tanhf(inn + r * hnn);
    float hold = h[(size_t)n * DD + c];
    float hv = (1.f - z) * nn + z * hold;

    __shared__ float sbuf[8];
    int lane = c & 31, w = c >> 5;
    float s = warpsum(hv);
    if (lane == 0) sbuf[w] = s;
    __syncthreads();
    float mu = 0.f;
#pragma unroll
    for (int i = 0; i < 8; i++) mu += sbuf[i];
    mu *= (1.f / 256.f);
    __syncthreads();
    float d0 = hv - mu;
    float s2 = warpsum(d0 * d0);
    if (lane == 0) sbuf[w] = s2;
    __syncthreads();
    float var = 0.f;
#pragma unroll
    for (int i = 0; i < 8; i++) var += sbuf[i];
    var *= (1.f / 256.f);

    float o = d0 * rsqrtf(var + EPS) * lng[c] + lnb[c];

    size_t idx = (size_t)n * DD + c;
    h[idx] = o;
    if (first) { m[idx] = o; e[idx] = o; }
    else       { m[idx] *= o; e[idx] += o; }
}

// ---------------- contiguous segment max ----------------
__global__ void segmax_kernel(const float* __restrict__ v, float* __restrict__ out, int slot) {
    int g = blockIdx.x;
    int c = threadIdx.x;
    int s = g_segs[g], t = g_sege[g];
    float mx = -INFINITY;
    for (int n = s; n < t; n++)
        mx = fmaxf(mx, v[(size_t)n * DD + c]);
    out[(size_t)g * OUTW + slot * DD + c] = mx;
}

// ---------------- launch ----------------
extern "C" void kernel_launch(void* const* d_in, const int* in_sizes, int n_in,
                              void* d_out, int out_size) {
    const float* x       = (const float*)d_in[0];
    const float* lin1_w  = (const float*)d_in[1];
    const float* lin1_b  = (const float*)d_in[2];
    const float* lin2_w  = (const float*)d_in[3];
    const float* lin2_b  = (const float*)d_in[4];
    const float* bn_g    = (const float*)d_in[5];
    const float* bn_b    = (const float*)d_in[6];
    const float* gru_wih = (const float*)d_in[7];
    const float* gru_whh = (const float*)d_in[8];
    const float* gru_bih = (const float*)d_in[9];
    const float* gru_bhh = (const float*)d_in[10];
    const float* ln_g    = (const float*)d_in[11];
    const float* ln_b    = (const float*)d_in[12];
    const int*   edges   = (const int*)d_in[13];
    const int*   batch   = (const int*)d_in[14];
    float* out = (float*)d_out;

    float* S = nullptr;
    cudaGetSymbolAddress((void**)&S, g_scratch);
    const size_t ND = (size_t)NN * DD;
    float* bh   = S;
    float* bagg = S + 1 * ND;
    float* bt1  = S + 2 * ND;
    float* bg   = S + 3 * ND;
    float* bm   = S + 4 * ND;
    float* be   = S + 5 * ND;
    float* bgi  = S + 6 * ND;
    float* bgh  = S + 9 * ND;

    static int smem_set = 0;
    if (!smem_set) {
        cudaFuncSetAttribute(gemm_mma, cudaFuncAttributeMaxDynamicSharedMemorySize, SMEM_DYN);
        smem_set = 1;
    }

    const int n4 = (int)(ND / 4);
    const int CP_BLOCKS = (n4 + 255) / 256;
    const int MT = (NN + 127) / 128;
    const dim3 grid_d(2, MT);    // O=256
    const dim3 grid_3d(6, MT);   // O=768

    vcopy4<<<CP_BLOCKS, 256>>>((const float4*)x, (float4*)bh, n4);
    seg_init_kernel<<<(GG + 255) / 256, 256>>>();
    seg_bounds_kernel<<<(NN + 255) / 256, 256>>>(batch);

    for (int i = 0; i < LLAYERS; i++) {
        vcopy4<<<CP_BLOCKS, 256>>>((const float4*)bh, (float4*)bagg, n4);
        edge_agg_kernel<<<EE, 256>>>(bh, edges, edges + EE, bagg);

        gemm_mma<<<grid_d, 256, SMEM_DYN>>>(bagg, lin1_w + (size_t)i * DD * DD,
                                            lin1_b + (size_t)i * DD, bt1, NN, DD, 1);
        gemm_mma<<<grid_d, 256, SMEM_DYN>>>(bt1, lin2_w + (size_t)i * DD * DD,
                                            lin2_b + (size_t)i * DD, bg, NN, DD, 1);

        bn_zero_kernel<<<1, 256>>>();
        bn_stats_kernel<<<(NN + 255) / 256, 256>>>(bg);
        bn_final_kernel<<<1, 256>>>(bn_g + (size_t)i * DD, bn_b + (size_t)i * DD);
        bn_apply_kernel<<<NN, 256>>>(bg);

        gemm_mma<<<grid_3d, 256, SMEM_DYN>>>(bg, gru_wih + (size_t)i * 3 * DD * DD,
                                             gru_bih + (size_t)i * 3 * DD, bgi, NN, 3 * DD, 0);
        gemm_mma<<<grid_3d, 256, SMEM_DYN>>>(bh, gru_whh + (size_t)i * 3 * DD * DD,
                                             gru_bhh + (size_t)i * 3 * DD, bgh, NN, 3 * DD, 0);

        gru_ln_kernel<<<NN, 256>>>(bgi, bgh, bh, ln_g, ln_b, bm, be, i == 0);

        segmax_kernel<<<GG, 256>>>(bh, out, i);
    }

    segmax_kernel<<<GG, 256>>>(bm, out, 3);
    segmax_kernel<<<GG, 256>>>(be, out, 4);
}

// round 8
// speedup vs baseline: 2.4391x; 1.4543x over previous
#include <cuda_runtime.h>
#include <cuda_fp16.h>
#include <cstdint>
#include <math.h>

#define NN 100000
#define DD 256
#define EE 320000
#define GG 4096
#define LLAYERS 3
#define OUTW 1280
#define EPS 1e-5f

// ---------------- scratch (device globals; no allocation) ----------------
// floats: bh 0, bagg 1, bg 2, bm 3, be 4, bgi 5(3), bgh 8(3), fp16 area 11..13
__device__ float g_scratch[13ULL * NN * DD];
__device__ __half g_w16[1600000];     // all weights as fp16
__device__ float g_bnsum[DD];
__device__ float g_bnsq[DD];
__device__ float g_scale[DD];
__device__ float g_shift[DD];
__device__ int   g_segs[GG];
__device__ int   g_sege[GG];

// ---------------- helpers ----------------
__device__ __forceinline__ uint32_t smem_u32(const void* p) {
    uint32_t a;
    asm("{ .reg .u64 t; cvta.to.shared.u64 t, %1; cvt.u32.u64 %0, t; }" : "=r"(a) : "l"(p));
    return a;
}
__device__ __forceinline__ void ldm_x4(uint32_t& r0, uint32_t& r1, uint32_t& r2, uint32_t& r3,
                                       uint32_t addr) {
    asm volatile("ldmatrix.sync.aligned.m8n8.x4.shared.b16 {%0,%1,%2,%3}, [%4];"
                 : "=r"(r0), "=r"(r1), "=r"(r2), "=r"(r3) : "r"(addr));
}
__device__ __forceinline__ void mma_f16(float* d, const uint32_t* a, const uint32_t* b) {
    asm volatile("mma.sync.aligned.m16n8k16.row.col.f32.f16.f16.f32 "
                 "{%0,%1,%2,%3}, {%4,%5,%6,%7}, {%8,%9}, {%0,%1,%2,%3};"
                 : "+f"(d[0]), "+f"(d[1]), "+f"(d[2]), "+f"(d[3])
                 : "r"(a[0]), "r"(a[1]), "r"(a[2]), "r"(a[3]), "r"(b[0]), "r"(b[1]));
}
#define CP16(dst, src) asm volatile("cp.async.ca.shared.global [%0], [%1], 16;" :: "r"(dst), "l"(src))
#define CPCOMMIT()     asm volatile("cp.async.commit_group;")
#define CPWAIT(n)      asm volatile("cp.async.wait_group %0;" :: "n"(n))

// SMEM: pitch 144 B per row (72 halfs); buf = 128*144 = 18432 B.
// stage s: A at s*36864, B at s*36864+18432. 2 stages -> 73728 B.
#define PITCHB 144
#define BUFSZ 18432
#define STAGESZ 36864
#define SMEM_DYN 73728

// ---------------- fp16 mma GEMM: C[M,O] = A[M,256] @ W[O,256]^T + bias ----------------
// CTA tile 128x128, 8 warps (4M x 2N, warp tile 32x64), K chunk 64, cp.async dbl-buffer.
__global__ __launch_bounds__(256, 2) void gemm16(
    const __half* __restrict__ A, const __half* __restrict__ W,
    const float* __restrict__ bias, float* __restrict__ C, __half* __restrict__ C16,
    int M, int O, int doRelu)
{
    extern __shared__ char smem[];
    const uint32_t sb = smem_u32(smem);
    const int tid = threadIdx.x, lane = tid & 31, wid = tid >> 5;
    const int rowBase = blockIdx.y * 128, colBase = blockIdx.x * 128;
    const int wm = (wid & 3) * 32, wn = (wid >> 2) * 64;

    // staging: thread t -> row t>>1, 64-byte half (t&1); 4 x cp.async(16B) per matrix per chunk
    const int srow = tid >> 1, shalf = tid & 1;
    const char* Asrc = (const char*)(A + (size_t)min(rowBase + srow, M - 1) * DD) + shalf * 64;
    const char* Bsrc = (const char*)(W + (size_t)(colBase + srow) * DD) + shalf * 64;
    const uint32_t stsA = sb + srow * PITCHB + shalf * 64;
    const uint32_t stsB = stsA + BUFSZ;

    // ldmatrix lane bases
    const uint32_t aAddr = sb + (wm + (lane & 7) + ((lane >> 3) & 1) * 8) * PITCHB + (lane >> 4) * 16;
    const uint32_t bAddr = sb + BUFSZ + (wn + (lane & 7) + (lane >> 4) * 8) * PITCHB + ((lane >> 3) & 1) * 16;

    float acc[2][8][4];
#pragma unroll
    for (int mt = 0; mt < 2; mt++)
#pragma unroll
        for (int nt = 0; nt < 8; nt++)
#pragma unroll
            for (int q = 0; q < 4; q++) acc[mt][nt][q] = 0.f;

    // issue chunk c into stage c&1 (chunk = 64 halfs = 128 bytes per row)
#define ISSUE(c) do {                                                     \
        uint32_t off = ((c) & 1) * STAGESZ;                               \
        const char* as = Asrc + (c) * 128;                                \
        const char* bs = Bsrc + (c) * 128;                                \
        CP16(stsA + off +  0, as +  0); CP16(stsB + off +  0, bs +  0);   \
        CP16(stsA + off + 16, as + 16); CP16(stsB + off + 16, bs + 16);   \
        CP16(stsA + off + 32, as + 32); CP16(stsB + off + 32, bs + 32);   \
        CP16(stsA + off + 48, as + 48); CP16(stsB + off + 48, bs + 48);   \
        CPCOMMIT();                                                       \
    } while (0)

    ISSUE(0);
#pragma unroll 1
    for (int c = 0; c < 4; c++) {
        if (c < 3) { ISSUE(c + 1); CPWAIT(1); } else { CPWAIT(0); }
        __syncthreads();
        const uint32_t off = (c & 1) * STAGESZ;
#pragma unroll
        for (int ks = 0; ks < 4; ks++) {
            const uint32_t ka = off + ks * 32;
            uint32_t af[2][4];
            ldm_x4(af[0][0], af[0][1], af[0][2], af[0][3], aAddr + ka);
            ldm_x4(af[1][0], af[1][1], af[1][2], af[1][3], aAddr + ka + 16 * PITCHB);
            uint32_t bf[8][2];
#pragma unroll
            for (int p = 0; p < 4; p++) {
                uint32_t r0, r1, r2, r3;
                ldm_x4(r0, r1, r2, r3, bAddr + ka + p * 16 * PITCHB);
                bf[2 * p][0] = r0;     bf[2 * p][1] = r1;
                bf[2 * p + 1][0] = r2; bf[2 * p + 1][1] = r3;
            }
#pragma unroll
            for (int mt = 0; mt < 2; mt++)
#pragma unroll
                for (int nt = 0; nt < 8; nt++)
                    mma_f16(acc[mt][nt], af[mt], bf[nt]);
        }
        __syncthreads();
    }

    // ---- epilogue ----
    const int g = lane >> 2, tig = lane & 3;
#pragma unroll
    for (int mt = 0; mt < 2; mt++) {
#pragma unroll
        for (int nt = 0; nt < 8; nt++) {
            int col = colBase + wn + nt * 8 + tig * 2;
            float2 bb = *(const float2*)(bias + col);
            int r0 = rowBase + wm + mt * 16 + g;
            int r1 = r0 + 8;
            float2 v0 = { acc[mt][nt][0] + bb.x, acc[mt][nt][1] + bb.y };
            float2 v1 = { acc[mt][nt][2] + bb.x, acc[mt][nt][3] + bb.y };
            if (doRelu) {
                v0.x = fmaxf(v0.x, 0.f); v0.y = fmaxf(v0.y, 0.f);
                v1.x = fmaxf(v1.x, 0.f); v1.y = fmaxf(v1.y, 0.f);
            }
            if (C16) {
                if (r0 < M) *(__half2*)(C16 + (size_t)r0 * O + col) = __floats2half2_rn(v0.x, v0.y);
                if (r1 < M) *(__half2*)(C16 + (size_t)r1 * O + col) = __floats2half2_rn(v1.x, v1.y);
            } else {
                if (r0 < M) *(float2*)(C + (size_t)r0 * O + col) = v0;
                if (r1 < M) *(float2*)(C + (size_t)r1 * O + col) = v1;
            }
        }
    }
}

// ---------------- conversion / utility kernels ----------------
__global__ void f2h_kernel(const float* __restrict__ s, __half* __restrict__ d, int n) {
    int i = (blockIdx.x * blockDim.x + threadIdx.x) * 8;
    if (i >= n) return;
    float4 a = *(const float4*)(s + i);
    float4 b = *(const float4*)(s + i + 4);
    __half2 r[4] = { __floats2half2_rn(a.x, a.y), __floats2half2_rn(a.z, a.w),
                     __floats2half2_rn(b.x, b.y), __floats2half2_rn(b.z, b.w) };
    *(float4*)(d + i) = *(float4*)r;
}

__global__ void vcopy4(const float4* __restrict__ src, float4* __restrict__ dst, int n4) {
    int i = blockIdx.x * blockDim.x + threadIdx.x;
    if (i < n4) dst[i] = src[i];
}

__global__ void seg_init_kernel() {
    int g = blockIdx.x * blockDim.x + threadIdx.x;
    if (g < GG) { g_segs[g] = 0; g_sege[g] = 0; }
}

__global__ void seg_bounds_kernel(const int* __restrict__ batch) {
    int i = blockIdx.x * blockDim.x + threadIdx.x;
    if (i >= NN) return;
    int b = batch[i];
    if (i == 0 || batch[i - 1] != b) g_segs[b] = i;
    if (i == NN - 1 || batch[i + 1] != b) g_sege[b] = i + 1;
}

__global__ void bn_zero_kernel() {
    int c = threadIdx.x;
    if (c < DD) { g_bnsum[c] = 0.f; g_bnsq[c] = 0.f; }
}

__global__ void bn_stats_kernel(const float* __restrict__ gbuf) {
    int c = threadIdx.x;
    int r0 = blockIdx.x * 256;
    int r1 = min(r0 + 256, NN);
    float s = 0.f, s2 = 0.f;
    for (int r = r0; r < r1; r++) {
        float v = gbuf[(size_t)r * DD + c];
        s += v; s2 += v * v;
    }
    atomicAdd(&g_bnsum[c], s);
    atomicAdd(&g_bnsq[c], s2);
}

__global__ void bn_final_kernel(const float* __restrict__ bng, const float* __restrict__ bnb) {
    int c = threadIdx.x;
    if (c >= DD) return;
    float invN = 1.f / (float)NN;
    float mean = g_bnsum[c] * invN;
    float var  = g_bnsq[c] * invN - mean * mean;
    float sc   = bng[c] * rsqrtf(var + EPS);
    g_scale[c] = sc;
    g_shift[c] = bnb[c] - mean * sc;
}

// BN affine, fp16 output: g16 = h2( g*scale + shift )
__global__ void bn_apply16_kernel(const float* __restrict__ gbuf, __half* __restrict__ g16) {
    int c = threadIdx.x;
    size_t idx = (size_t)blockIdx.x * DD + c;
    g16[idx] = __float2half(fmaf(gbuf[idx], g_scale[c], g_shift[c]));
}

__global__ void edge_agg_kernel(const float* __restrict__ h,
                                const int* __restrict__ src,
                                const int* __restrict__ dst,
                                float* __restrict__ agg) {
    int eid = blockIdx.x;
    int s = __ldg(&src[eid]);
    int d = __ldg(&dst[eid]);
    int c = threadIdx.x;
    atomicAdd(&agg[(size_t)d * DD + c], __ldg(&h[(size_t)s * DD + c]));
}

// ---------------- GRU gates + LayerNorm + m/e; writes h (fp32) and h16 ----------------
__inline__ __device__ float warpsum(float v) {
#pragma unroll
    for (int o = 16; o > 0; o >>= 1) v += __shfl_xor_sync(0xffffffffu, v, o);
    return v;
}

__global__ __launch_bounds__(256) void gru_ln_kernel(
    const float* __restrict__ gi, const float* __restrict__ gh,
    float* __restrict__ h, __half* __restrict__ h16,
    const float* __restrict__ lng, const float* __restrict__ lnb,
    float* __restrict__ m, float* __restrict__ e, int first)
{
    int n = blockIdx.x;
    int c = threadIdx.x;
    const float* gin = gi + (size_t)n * 768;
    const float* ghn = gh + (size_t)n * 768;

    float ir = gin[c], iz = gin[256 + c], inn = gin[512 + c];
    float hr = ghn[c], hz = ghn[256 + c], hnn = ghn[512 + c];
    float r  = 1.f / (1.f + expf(-(ir + hr)));
    float z  = 1.f / (1.f + expf(-(iz + hz)));
    float nn = tanhf(inn + r * hnn);
    float hold = h[(size_t)n * DD + c];
    float hv = (1.f - z) * nn + z * hold;

    __shared__ float sbuf[8];
    int lane = c & 31, w = c >> 5;
    float s = warpsum(hv);
    if (lane == 0) sbuf[w] = s;
    __syncthreads();
    float mu = 0.f;
#pragma unroll
    for (int i = 0; i < 8; i++) mu += sbuf[i];
    mu *= (1.f / 256.f);
    __syncthreads();
    float d0 = hv - mu;
    float s2 = warpsum(d0 * d0);
    if (lane == 0) sbuf[w] = s2;
    __syncthreads();
    float var = 0.f;
#pragma unroll
    for (int i = 0; i < 8; i++) var += sbuf[i];
    var *= (1.f / 256.f);

    float o = d0 * rsqrtf(var + EPS) * lng[c] + lnb[c];

    size_t idx = (size_t)n * DD + c;
    h[idx] = o;
    h16[idx] = __float2half(o);
    if (first) { m[idx] = o; e[idx] = o; }
    else       { m[idx] *= o; e[idx] += o; }
}

// ---------------- contiguous segment max ----------------
__global__ void segmax_kernel(const float* __restrict__ v, float* __restrict__ out, int slot) {
    int g = blockIdx.x;
    int c = threadIdx.x;
    int s = g_segs[g], t = g_sege[g];
    float mx = -INFINITY;
    for (int n = s; n < t; n++)
        mx = fmaxf(mx, v[(size_t)n * DD + c]);
    out[(size_t)g * OUTW + slot * DD + c] = mx;
}

// ---------------- launch ----------------
extern "C" void kernel_launch(void* const* d_in, const int* in_sizes, int n_in,
                              void* d_out, int out_size) {
    const float* x       = (const float*)d_in[0];
    const float* lin1_w  = (const float*)d_in[1];
    const float* lin1_b  = (const float*)d_in[2];
    const float* lin2_w  = (const float*)d_in[3];
    const float* lin2_b  = (const float*)d_in[4];
    const float* bn_g    = (const float*)d_in[5];
    const float* bn_b    = (const float*)d_in[6];
    const float* gru_wih = (const float*)d_in[7];
    const float* gru_whh = (const float*)d_in[8];
    const float* gru_bih = (const float*)d_in[9];
    const float* gru_bhh = (const float*)d_in[10];
    const float* ln_g    = (const float*)d_in[11];
    const float* ln_b    = (const float*)d_in[12];
    const int*   edges   = (const int*)d_in[13];
    const int*   batch   = (const int*)d_in[14];
    float* out = (float*)d_out;

    float* S = nullptr;
    cudaGetSymbolAddress((void**)&S, g_scratch);
    __half* W16 = nullptr;
    cudaGetSymbolAddress((void**)&W16, g_w16);

    const size_t ND = (size_t)NN * DD;
    float* bh   = S;
    float* bagg = S + 1 * ND;
    float* bg   = S + 2 * ND;
    float* bm   = S + 3 * ND;
    float* be   = S + 4 * ND;
    float* bgi  = S + 5 * ND;
    float* bgh  = S + 8 * ND;
    __half* bagg16 = (__half*)(S + 11 * ND);
    __half* bt1_16 = bagg16 + ND;
    __half* bg16   = bagg16 + 2 * ND;
    __half* bh16   = bagg16 + 3 * ND;

    // fp16 weight layout inside g_w16
    const size_t WD = (size_t)DD * DD;         // 65536
    __half* w1_16  = W16;                       // L*WD
    __half* w2_16  = W16 + LLAYERS * WD;        // L*WD
    __half* wih16  = W16 + 2 * LLAYERS * WD;    // L*3*WD
    __half* whh16  = W16 + 2 * LLAYERS * WD + 3 * LLAYERS * WD;

    static int smem_set = 0;
    if (!smem_set) {
        cudaFuncSetAttribute(gemm16, cudaFuncAttributeMaxDynamicSharedMemorySize, SMEM_DYN);
        smem_set = 1;
    }

    const int n4 = (int)(ND / 4);
    const int CP_BLOCKS = (n4 + 255) / 256;
    const int F2H_ND_BLOCKS = (int)((ND / 8 + 255) / 256);
    const int MT = (NN + 127) / 128;
    const dim3 grid_d(2, MT);    // O=256
    const dim3 grid_3d(6, MT);   // O=768

    // one-time conversions: weights + x
    {
        int nw = LLAYERS * (int)WD;
        f2h_kernel<<<(nw / 8 + 255) / 256, 256>>>(lin1_w, w1_16, nw);
        f2h_kernel<<<(nw / 8 + 255) / 256, 256>>>(lin2_w, w2_16, nw);
        int nw3 = 3 * nw;
        f2h_kernel<<<(nw3 / 8 + 255) / 256, 256>>>(gru_wih, wih16, nw3);
        f2h_kernel<<<(nw3 / 8 + 255) / 256, 256>>>(gru_whh, whh16, nw3);
    }
    vcopy4<<<CP_BLOCKS, 256>>>((const float4*)x, (float4*)bh, n4);
    f2h_kernel<<<F2H_ND_BLOCKS, 256>>>(x, bh16, (int)ND);
    seg_init_kernel<<<(GG + 255) / 256, 256>>>();
    seg_bounds_kernel<<<(NN + 255) / 256, 256>>>(batch);

    for (int i = 0; i < LLAYERS; i++) {
        // agg = h + scatter-add; then fp16 copy
        vcopy4<<<CP_BLOCKS, 256>>>((const float4*)bh, (float4*)bagg, n4);
        edge_agg_kernel<<<EE, 256>>>(bh, edges, edges + EE, bagg);
        f2h_kernel<<<F2H_ND_BLOCKS, 256>>>(bagg, bagg16, (int)ND);

        // t1 = relu(agg @ W1^T + b1) -> fp16 ; g = relu(t1 @ W2^T + b2) -> fp32
        gemm16<<<grid_d, 256, SMEM_DYN>>>(bagg16, w1_16 + i * WD,
                                          lin1_b + (size_t)i * DD, nullptr, bt1_16, NN, DD, 1);
        gemm16<<<grid_d, 256, SMEM_DYN>>>(bt1_16, w2_16 + i * WD,
                                          lin2_b + (size_t)i * DD, bg, nullptr, NN, DD, 1);

        // BatchNorm stats + fp16 normalized output
        bn_zero_kernel<<<1, 256>>>();
        bn_stats_kernel<<<(NN + 255) / 256, 256>>>(bg);
        bn_final_kernel<<<1, 256>>>(bn_g + (size_t)i * DD, bn_b + (size_t)i * DD);
        bn_apply16_kernel<<<NN, 256>>>(bg, bg16);

        // GRU matmuls (fp32 outputs)
        gemm16<<<grid_3d, 256, SMEM_DYN>>>(bg16, wih16 + (size_t)i * 3 * WD,
                                           gru_bih + (size_t)i * 3 * DD, bgi, nullptr, NN, 3 * DD, 0);
        gemm16<<<grid_3d, 256, SMEM_DYN>>>(bh16, whh16 + (size_t)i * 3 * WD,
                                           gru_bhh + (size_t)i * 3 * DD, bgh, nullptr, NN, 3 * DD, 0);

        // gates + LayerNorm + m/e; writes bh and bh16
        gru_ln_kernel<<<NN, 256>>>(bgi, bgh, bh, bh16, ln_g, ln_b, bm, be, i == 0);

        segmax_kernel<<<GG, 256>>>(bh, out, i);
    }

    segmax_kernel<<<GG, 256>>>(bm, out, 3);
    segmax_kernel<<<GG, 256>>>(be, out, 4);
}

// round 9
// speedup vs baseline: 2.5849x; 1.0598x over previous
#include <cuda_runtime.h>
#include <cuda_fp16.h>
#include <cstdint>
#include <math.h>

#define NN 100000
#define DD 256
#define EE 320000
#define GG 4096
#define LLAYERS 3
#define OUTW 1280
#define EPS 1e-5f

// ---------------- scratch (device globals; no allocation) ----------------
// fp32 slots: bh 0, bg 1, bm 2, be 3, bgi 4(3), bgh 7(3); fp16 at slot 10..11
__device__ float g_scratch[12ULL * NN * DD];
__device__ __half g_w16[1600000];
__device__ float g_bnsum[DD];
__device__ float g_bnsq[DD];
__device__ float g_scale[DD];
__device__ float g_shift[DD];
// CSR
__device__ int g_deg[NN];
__device__ int g_off[NN + 1];
__device__ int g_cur[NN];
__device__ int g_csr[EE];

// ---------------- helpers ----------------
__device__ __forceinline__ uint32_t smem_u32(const void* p) {
    uint32_t a;
    asm("{ .reg .u64 t; cvta.to.shared.u64 t, %1; cvt.u32.u64 %0, t; }" : "=r"(a) : "l"(p));
    return a;
}
__device__ __forceinline__ void ldm_x4(uint32_t& r0, uint32_t& r1, uint32_t& r2, uint32_t& r3,
                                       uint32_t addr) {
    asm volatile("ldmatrix.sync.aligned.m8n8.x4.shared.b16 {%0,%1,%2,%3}, [%4];"
                 : "=r"(r0), "=r"(r1), "=r"(r2), "=r"(r3) : "r"(addr));
}
__device__ __forceinline__ void mma_f16(float* d, const uint32_t* a, const uint32_t* b) {
    asm volatile("mma.sync.aligned.m16n8k16.row.col.f32.f16.f16.f32 "
                 "{%0,%1,%2,%3}, {%4,%5,%6,%7}, {%8,%9}, {%0,%1,%2,%3};"
                 : "+f"(d[0]), "+f"(d[1]), "+f"(d[2]), "+f"(d[3])
                 : "r"(a[0]), "r"(a[1]), "r"(a[2]), "r"(a[3]), "r"(b[0]), "r"(b[1]));
}
#define CP16(dst, src) asm volatile("cp.async.ca.shared.global [%0], [%1], 16;" :: "r"(dst), "l"(src))
#define CPCOMMIT()     asm volatile("cp.async.commit_group;")
#define CPWAIT(n)      asm volatile("cp.async.wait_group %0;" :: "n"(n))

// ordered-uint float key for atomicMax-based segment max
__device__ __forceinline__ unsigned fkey(float f) {
    unsigned u = __float_as_uint(f);
    return (u & 0x80000000u) ? ~u : (u | 0x80000000u);
}

// SMEM: pitch 144 B per row; buf = 128*144 = 18432 B; stage = A+B = 36864; 3 stages.
#define PITCHB 144
#define BUFSZ 18432
#define STAGESZ 36864
#define SMEM_DYN 110592

// ---------------- fp16 mma GEMM: C[M,O] = A[M,256] @ W[O,256]^T + bias ----------------
__global__ __launch_bounds__(256, 2) void gemm16(
    const __half* __restrict__ A, const __half* __restrict__ W,
    const float* __restrict__ bias, float* __restrict__ C, __half* __restrict__ C16,
    int M, int O, int doRelu)
{
    extern __shared__ char smem[];
    const uint32_t sb = smem_u32(smem);
    const int tid = threadIdx.x, lane = tid & 31, wid = tid >> 5;
    const int rowBase = blockIdx.y * 128, colBase = blockIdx.x * 128;
    const int wm = (wid & 3) * 32, wn = (wid >> 2) * 64;

    const int srow = tid >> 1, shalf = tid & 1;
    const char* Asrc = (const char*)(A + (size_t)min(rowBase + srow, M - 1) * DD) + shalf * 64;
    const char* Bsrc = (const char*)(W + (size_t)(colBase + srow) * DD) + shalf * 64;
    const uint32_t stsA = sb + srow * PITCHB + shalf * 64;
    const uint32_t stsB = stsA + BUFSZ;

    const uint32_t aAddr = sb + (wm + (lane & 7) + ((lane >> 3) & 1) * 8) * PITCHB + (lane >> 4) * 16;
    const uint32_t bAddr = sb + BUFSZ + (wn + (lane & 7) + (lane >> 4) * 8) * PITCHB + ((lane >> 3) & 1) * 16;

    float acc[2][8][4];
#pragma unroll
    for (int mt = 0; mt < 2; mt++)
#pragma unroll
        for (int nt = 0; nt < 8; nt++)
#pragma unroll
            for (int q = 0; q < 4; q++) acc[mt][nt][q] = 0.f;

#define ISSUE(c) do {                                                     \
        uint32_t off = ((c) % 3) * STAGESZ;                               \
        const char* as = Asrc + (c) * 128;                                \
        const char* bs = Bsrc + (c) * 128;                                \
        CP16(stsA + off +  0, as +  0); CP16(stsB + off +  0, bs +  0);   \
        CP16(stsA + off + 16, as + 16); CP16(stsB + off + 16, bs + 16);   \
        CP16(stsA + off + 32, as + 32); CP16(stsB + off + 32, bs + 32);   \
        CP16(stsA + off + 48, as + 48); CP16(stsB + off + 48, bs + 48);   \
        CPCOMMIT();                                                       \
    } while (0)

    ISSUE(0); ISSUE(1);
#pragma unroll 1
    for (int c = 0; c < 4; c++) {
        if (c < 3) { CPWAIT(1); } else { CPWAIT(0); }
        __syncthreads();                     // chunk c landed; everyone done with c-1
        if (c < 2) ISSUE(c + 2);             // overwrite stage (c-1)%3 — safe
        const uint32_t off = (c % 3) * STAGESZ;
#pragma unroll
        for (int ks = 0; ks < 4; ks++) {
            const uint32_t ka = off + ks * 32;
            uint32_t af[2][4];
            ldm_x4(af[0][0], af[0][1], af[0][2], af[0][3], aAddr + ka);
            ldm_x4(af[1][0], af[1][1], af[1][2], af[1][3], aAddr + ka + 16 * PITCHB);
            uint32_t bf[8][2];
#pragma unroll
            for (int p = 0; p < 4; p++) {
                uint32_t r0, r1, r2, r3;
                ldm_x4(r0, r1, r2, r3, bAddr + ka + p * 16 * PITCHB);
                bf[2 * p][0] = r0;     bf[2 * p][1] = r1;
                bf[2 * p + 1][0] = r2; bf[2 * p + 1][1] = r3;
            }
#pragma unroll
            for (int mt = 0; mt < 2; mt++)
#pragma unroll
                for (int nt = 0; nt < 8; nt++)
                    mma_f16(acc[mt][nt], af[mt], bf[nt]);
        }
    }

    // ---- epilogue ----
    const int g = lane >> 2, tig = lane & 3;
#pragma unroll
    for (int mt = 0; mt < 2; mt++) {
#pragma unroll
        for (int nt = 0; nt < 8; nt++) {
            int col = colBase + wn + nt * 8 + tig * 2;
            float2 bb = *(const float2*)(bias + col);
            int r0 = rowBase + wm + mt * 16 + g;
            int r1 = r0 + 8;
            float2 v0 = { acc[mt][nt][0] + bb.x, acc[mt][nt][1] + bb.y };
            float2 v1 = { acc[mt][nt][2] + bb.x, acc[mt][nt][3] + bb.y };
            if (doRelu) {
                v0.x = fmaxf(v0.x, 0.f); v0.y = fmaxf(v0.y, 0.f);
                v1.x = fmaxf(v1.x, 0.f); v1.y = fmaxf(v1.y, 0.f);
            }
            if (C16) {
                if (r0 < M) *(__half2*)(C16 + (size_t)r0 * O + col) = __floats2half2_rn(v0.x, v0.y);
                if (r1 < M) *(__half2*)(C16 + (size_t)r1 * O + col) = __floats2half2_rn(v1.x, v1.y);
            } else {
                if (r0 < M) *(float2*)(C + (size_t)r0 * O + col) = v0;
                if (r1 < M) *(float2*)(C + (size_t)r1 * O + col) = v1;
            }
        }
    }
}

// ---------------- conversions / CSR / utility ----------------
__global__ void f2h_kernel(const float* __restrict__ s, __half* __restrict__ d, int n) {
    int i = (blockIdx.x * blockDim.x + threadIdx.x) * 8;
    if (i >= n) return;
    float4 a = *(const float4*)(s + i);
    float4 b = *(const float4*)(s + i + 4);
    __half2 r[4] = { __floats2half2_rn(a.x, a.y), __floats2half2_rn(a.z, a.w),
                     __floats2half2_rn(b.x, b.y), __floats2half2_rn(b.z, b.w) };
    *(float4*)(d + i) = *(float4*)r;
}

__global__ void vcopy4(const float4* __restrict__ src, float4* __restrict__ dst, int n4) {
    int i = blockIdx.x * blockDim.x + threadIdx.x;
    if (i < n4) dst[i] = src[i];
}

__global__ void csr_zero_kernel() {
    int i = blockIdx.x * blockDim.x + threadIdx.x;
    if (i < NN) g_deg[i] = 0;
}
__global__ void csr_hist_kernel(const int* __restrict__ dst) {
    int e = blockIdx.x * blockDim.x + threadIdx.x;
    if (e < EE) atomicAdd(&g_deg[dst[e]], 1);
}
// single-block exclusive scan of g_deg -> g_off, g_cur; sentinel g_off[NN]=EE
__global__ void csr_scan_kernel() {
    __shared__ int warpsums[32];
    __shared__ int sbase;
    int tid = threadIdx.x;
    if (tid == 0) sbase = 0;
    __syncthreads();
    for (int start = 0; start < NN; start += 1024) {
        int i = start + tid;
        int v = (i < NN) ? g_deg[i] : 0;
        int x = v;
#pragma unroll
        for (int o = 1; o < 32; o <<= 1) {
            int t = __shfl_up_sync(~0u, x, o);
            if ((tid & 31) >= o) x += t;
        }
        if ((tid & 31) == 31) warpsums[tid >> 5] = x;
        __syncthreads();
        if (tid < 32) {
            int w = warpsums[tid];
#pragma unroll
            for (int o = 1; o < 32; o <<= 1) {
                int t = __shfl_up_sync(~0u, w, o);
                if (tid >= o) w += t;
            }
            warpsums[tid] = w;
        }
        __syncthreads();
        int ex = x - v + ((tid >= 32) ? warpsums[(tid >> 5) - 1] : 0) + sbase;
        if (i < NN) { g_off[i] = ex; g_cur[i] = ex; }
        __syncthreads();
        if (tid == 0) sbase += warpsums[31];
        __syncthreads();
    }
    if (tid == 0) g_off[NN] = sbase;
}
__global__ void csr_scatter_kernel(const int* __restrict__ src, const int* __restrict__ dst) {
    int e = blockIdx.x * blockDim.x + threadIdx.x;
    if (e >= EE) return;
    int pos = atomicAdd(&g_cur[dst[e]], 1);
    g_csr[pos] = src[e];
}

// agg16[n] = fp16( h[n] + sum_{j in N(n)} h[j] ), fp32 accumulation
__global__ __launch_bounds__(256) void gather_agg16(const float* __restrict__ h,
                                                    __half* __restrict__ agg16) {
    int n = blockIdx.x, c = threadIdx.x;
    float s = h[(size_t)n * DD + c];
    int beg = g_off[n], end = g_off[n + 1];
    for (int j = beg; j < end; j++) {
        int sidx = __ldg(&g_csr[j]);
        s += __ldg(&h[(size_t)sidx * DD + c]);
    }
    agg16[(size_t)n * DD + c] = __float2half(s);
}

__global__ void bn_zero_kernel() {
    int c = threadIdx.x;
    if (c < DD) { g_bnsum[c] = 0.f; g_bnsq[c] = 0.f; }
}
__global__ void bn_stats_kernel(const float* __restrict__ gbuf) {
    int c = threadIdx.x;
    int r0 = blockIdx.x * 256;
    int r1 = min(r0 + 256, NN);
    float s = 0.f, s2 = 0.f;
    for (int r = r0; r < r1; r++) {
        float v = gbuf[(size_t)r * DD + c];
        s += v; s2 += v * v;
    }
    atomicAdd(&g_bnsum[c], s);
    atomicAdd(&g_bnsq[c], s2);
}
__global__ void bn_final_kernel(const float* __restrict__ bng, const float* __restrict__ bnb) {
    int c = threadIdx.x;
    if (c >= DD) return;
    float invN = 1.f / (float)NN;
    float mean = g_bnsum[c] * invN;
    float var  = g_bnsq[c] * invN - mean * mean;
    float sc   = bng[c] * rsqrtf(var + EPS);
    g_scale[c] = sc;
    g_shift[c] = bnb[c] - mean * sc;
}
__global__ void bn_apply16_kernel(const float* __restrict__ gbuf, __half* __restrict__ g16) {
    int c = threadIdx.x;
    size_t idx = (size_t)blockIdx.x * DD + c;
    g16[idx] = __float2half(fmaf(gbuf[idx], g_scale[c], g_shift[c]));
}

// ---------------- GRU gates + LayerNorm + m/e + fused segment-max ----------------
__inline__ __device__ float warpsum(float v) {
#pragma unroll
    for (int o = 16; o > 0; o >>= 1) v += __shfl_xor_sync(0xffffffffu, v, o);
    return v;
}

__global__ __launch_bounds__(256) void gru_ln_kernel(
    const float* __restrict__ gi, const float* __restrict__ gh,
    float* __restrict__ h, __half* __restrict__ h16,
    const float* __restrict__ lng, const float* __restrict__ lnb,
    float* __restrict__ m, float* __restrict__ e,
    const int* __restrict__ batch, unsigned* __restrict__ outk, int layer)
{
    int n = blockIdx.x;
    int c = threadIdx.x;
    const float* gin = gi + (size_t)n * 768;
    const float* ghn = gh + (size_t)n * 768;

    float ir = gin[c], iz = gin[256 + c], inn = gin[512 + c];
    float hr = ghn[c], hz = ghn[256 + c], hnn = ghn[512 + c];
    float r  = 1.f / (1.f + expf(-(ir + hr)));
    float z  = 1.f / (1.f + expf(-(iz + hz)));
    float nn = tanhf(inn + r * hnn);
    float hold = h[(size_t)n * DD + c];
    float hv = (1.f - z) * nn + z * hold;

    __shared__ float sbuf[8];
    int lane = c & 31, w = c >> 5;
    float s = warpsum(hv);
    if (lane == 0) sbuf[w] = s;
    __syncthreads();
    float mu = 0.f;
#pragma unroll
    for (int i = 0; i < 8; i++) mu += sbuf[i];
    mu *= (1.f / 256.f);
    __syncthreads();
    float d0 = hv - mu;
    float s2 = warpsum(d0 * d0);
    if (lane == 0) sbuf[w] = s2;
    __syncthreads();
    float var = 0.f;
#pragma unroll
    for (int i = 0; i < 8; i++) var += sbuf[i];
    var *= (1.f / 256.f);

    float o = d0 * rsqrtf(var + EPS) * lng[c] + lnb[c];

    size_t idx = (size_t)n * DD + c;
    h[idx] = o;
    h16[idx] = __float2half(o);
    float mv, ev;
    if (layer == 0) { mv = o; ev = o; }
    else            { mv = m[idx] * o; ev = e[idx] + o; }
    m[idx] = mv; e[idx] = ev;

    int b = __ldg(&batch[n]);
    unsigned* orow = outk + (size_t)b * OUTW;
    atomicMax(&orow[layer * DD + c], fkey(o));
    if (layer == LLAYERS - 1) {
        atomicMax(&orow[3 * DD + c], fkey(mv));
        atomicMax(&orow[4 * DD + c], fkey(ev));
    }
}

__global__ void out_init_kernel(unsigned* __restrict__ outk) {
    int i = blockIdx.x * blockDim.x + threadIdx.x;
    if (i < GG * OUTW) outk[i] = 0x007FFFFFu;   // key(-inf)
}
__global__ void out_finish_kernel(unsigned* __restrict__ outk) {
    int i = blockIdx.x * blockDim.x + threadIdx.x;
    if (i >= GG * OUTW) return;
    unsigned u = outk[i];
    unsigned bits = (u & 0x80000000u) ? (u ^ 0x80000000u) : ~u;
    outk[i] = bits;   // in-place: buffer is the float output
}

// ---------------- launch ----------------
extern "C" void kernel_launch(void* const* d_in, const int* in_sizes, int n_in,
                              void* d_out, int out_size) {
    const float* x       = (const float*)d_in[0];
    const float* lin1_w  = (const float*)d_in[1];
    const float* lin1_b  = (const float*)d_in[2];
    const float* lin2_w  = (const float*)d_in[3];
    const float* lin2_b  = (const float*)d_in[4];
    const float* bn_g    = (const float*)d_in[5];
    const float* bn_b    = (const float*)d_in[6];
    const float* gru_wih = (const float*)d_in[7];
    const float* gru_whh = (const float*)d_in[8];
    const float* gru_bih = (const float*)d_in[9];
    const float* gru_bhh = (const float*)d_in[10];
    const float* ln_g    = (const float*)d_in[11];
    const float* ln_b    = (const float*)d_in[12];
    const int*   edges   = (const int*)d_in[13];
    const int*   batch   = (const int*)d_in[14];
    unsigned* outk = (unsigned*)d_out;

    float* S = nullptr;
    cudaGetSymbolAddress((void**)&S, g_scratch);
    __half* W16 = nullptr;
    cudaGetSymbolAddress((void**)&W16, g_w16);

    const size_t ND = (size_t)NN * DD;
    float* bh   = S;
    float* bg   = S + 1 * ND;
    float* bm   = S + 2 * ND;
    float* be   = S + 3 * ND;
    float* bgi  = S + 4 * ND;
    float* bgh  = S + 7 * ND;
    __half* bagg16 = (__half*)(S + 10 * ND);
    __half* bt1_16 = bagg16 + ND;
    __half* bg16   = bagg16 + 2 * ND;
    __half* bh16   = bagg16 + 3 * ND;

    const size_t WD = (size_t)DD * DD;
    __half* w1_16 = W16;
    __half* w2_16 = W16 + LLAYERS * WD;
    __half* wih16 = W16 + 2 * LLAYERS * WD;
    __half* whh16 = W16 + 5 * LLAYERS * WD;

    static int smem_set = 0;
    if (!smem_set) {
        cudaFuncSetAttribute(gemm16, cudaFuncAttributeMaxDynamicSharedMemorySize, SMEM_DYN);
        smem_set = 1;
    }

    const int n4 = (int)(ND / 4);
    const int MT = (NN + 127) / 128;
    const dim3 grid_d(2, MT);
    const dim3 grid_3d(6, MT);

    // one-time conversions + init
    {
        int nw = LLAYERS * (int)WD;
        f2h_kernel<<<(nw / 8 + 255) / 256, 256>>>(lin1_w, w1_16, nw);
        f2h_kernel<<<(nw / 8 + 255) / 256, 256>>>(lin2_w, w2_16, nw);
        int nw3 = 3 * nw;
        f2h_kernel<<<(nw3 / 8 + 255) / 256, 256>>>(gru_wih, wih16, nw3);
        f2h_kernel<<<(nw3 / 8 + 255) / 256, 256>>>(gru_whh, whh16, nw3);
    }
    vcopy4<<<(n4 + 255) / 256, 256>>>((const float4*)x, (float4*)bh, n4);
    f2h_kernel<<<(int)((ND / 8 + 255) / 256), 256>>>(x, bh16, (int)ND);
    out_init_kernel<<<(GG * OUTW + 255) / 256, 256>>>(outk);

    // CSR build (edges[0..E)=src, edges[E..2E)=dst)
    csr_zero_kernel<<<(NN + 255) / 256, 256>>>();
    csr_hist_kernel<<<(EE + 255) / 256, 256>>>(edges + EE);
    csr_scan_kernel<<<1, 1024>>>();
    csr_scatter_kernel<<<(EE + 255) / 256, 256>>>(edges, edges + EE);

    for (int i = 0; i < LLAYERS; i++) {
        gather_agg16<<<NN, 256>>>(bh, bagg16);

        gemm16<<<grid_d, 256, SMEM_DYN>>>(bagg16, w1_16 + i * WD,
                                          lin1_b + (size_t)i * DD, nullptr, bt1_16, NN, DD, 1);
        gemm16<<<grid_d, 256, SMEM_DYN>>>(bt1_16, w2_16 + i * WD,
                                          lin2_b + (size_t)i * DD, bg, nullptr, NN, DD, 1);

        bn_zero_kernel<<<1, 256>>>();
        bn_stats_kernel<<<(NN + 255) / 256, 256>>>(bg);
        bn_final_kernel<<<1, 256>>>(bn_g + (size_t)i * DD, bn_b + (size_t)i * DD);
        bn_apply16_kernel<<<NN, 256>>>(bg, bg16);

        gemm16<<<grid_3d, 256, SMEM_DYN>>>(bg16, wih16 + (size_t)i * 3 * WD,
                                           gru_bih + (size_t)i * 3 * DD, bgi, nullptr, NN, 3 * DD, 0);
        gemm16<<<grid_3d, 256, SMEM_DYN>>>(bh16, whh16 + (size_t)i * 3 * WD,
                                           gru_bhh + (size_t)i * 3 * DD, bgh, nullptr, NN, 3 * DD, 0);

        gru_ln_kernel<<<NN, 256>>>(bgi, bgh, bh, bh16, ln_g, ln_b, bm, be, batch, outk, i);
    }

    out_finish_kernel<<<(GG * OUTW + 255) / 256, 256>>>(outk);
}

// round 11
// speedup vs baseline: 2.8591x; 1.1061x over previous
#include <cuda_runtime.h>
#include <cuda_fp16.h>
#include <cstdint>
#include <math.h>

#define NN 100000
#define DD 256
#define EE 320000
#define GG 4096
#define LLAYERS 3
#define OUTW 1280
#define EPS 1e-5f

// ---------------- scratch (device globals; no allocation) ----------------
// fp32 slots: bh 0, bg 1, bm 2, be 3, brz 4-5, bin 6, bhn 7; fp16 slots 8..10
__device__ float g_scratch[11ULL * NN * DD];
__device__ __half g_w16[2400000];
__device__ float g_brzb[LLAYERS * 512];
__device__ float g_bnsum[DD];
__device__ float g_bnsq[DD];
__device__ float g_scale[DD];
__device__ float g_shift[DD];
// CSR
__device__ int g_deg[NN];
__device__ int g_off[NN + 1];
__device__ int g_cur[NN];
__device__ int g_csr[EE];

// ---------------- helpers ----------------
__device__ __forceinline__ uint32_t smem_u32(const void* p) {
    uint32_t a;
    asm("{ .reg .u64 t; cvta.to.shared.u64 t, %1; cvt.u32.u64 %0, t; }" : "=r"(a) : "l"(p));
    return a;
}
__device__ __forceinline__ void ldm_x4(uint32_t& r0, uint32_t& r1, uint32_t& r2, uint32_t& r3,
                                       uint32_t addr) {
    asm volatile("ldmatrix.sync.aligned.m8n8.x4.shared.b16 {%0,%1,%2,%3}, [%4];"
                 : "=r"(r0), "=r"(r1), "=r"(r2), "=r"(r3) : "r"(addr));
}
__device__ __forceinline__ void mma_f16(float* d, const uint32_t* a, const uint32_t* b) {
    asm volatile("mma.sync.aligned.m16n8k16.row.col.f32.f16.f16.f32 "
                 "{%0,%1,%2,%3}, {%4,%5,%6,%7}, {%8,%9}, {%0,%1,%2,%3};"
                 : "+f"(d[0]), "+f"(d[1]), "+f"(d[2]), "+f"(d[3])
                 : "r"(a[0]), "r"(a[1]), "r"(a[2]), "r"(a[3]), "r"(b[0]), "r"(b[1]));
}
#define CP16(dst, src) asm volatile("cp.async.cg.shared.global [%0], [%1], 16;" :: "r"(dst), "l"(src))
#define CPCOMMIT()     asm volatile("cp.async.commit_group;")
#define CPWAIT(n)      asm volatile("cp.async.wait_group %0;" :: "n"(n))

__device__ __forceinline__ unsigned fkey(float f) {
    unsigned u = __float_as_uint(f);
    return (u & 0x80000000u) ? ~u : (u | 0x80000000u);
}

#define PITCHB 144
#define BUFSZ 18432
#define STAGESZ 36864
#define SMEM_DYN 110592

// ---------------- fp16 mma GEMM: C[M,O] = A[M,K](lda) @ W[O,K]^T + bias ----------------
__global__ __launch_bounds__(256, 2) void gemm16(
    const __half* __restrict__ A, int lda, const __half* __restrict__ W,
    const float* __restrict__ bias, float* __restrict__ C, __half* __restrict__ C16,
    int ldc, int M, int K, int doRelu)
{
    extern __shared__ char smem[];
    const uint32_t sb = smem_u32(smem);
    const int tid = threadIdx.x, lane = tid & 31, wid = tid >> 5;
    const int rowBase = blockIdx.y * 128, colBase = blockIdx.x * 128;
    const int wm = (wid & 3) * 32, wn = (wid >> 2) * 64;
    const int NCH = K >> 6;

    const int srow = tid >> 1, shalf = tid & 1;
    const char* Asrc = (const char*)(A + (size_t)min(rowBase + srow, M - 1) * lda) + shalf * 64;
    const char* Bsrc = (const char*)(W + (size_t)(colBase + srow) * K) + shalf * 64;
    const uint32_t stsA = sb + srow * PITCHB + shalf * 64;
    const uint32_t stsB = stsA + BUFSZ;

    const uint32_t aAddr = sb + (wm + (lane & 7) + ((lane >> 3) & 1) * 8) * PITCHB + (lane >> 4) * 16;
    const uint32_t bAddr = sb + BUFSZ + (wn + (lane & 7) + (lane >> 4) * 8) * PITCHB + ((lane >> 3) & 1) * 16;

    float acc[2][8][4];
#pragma unroll
    for (int mt = 0; mt < 2; mt++)
#pragma unroll
        for (int nt = 0; nt < 8; nt++)
#pragma unroll
            for (int q = 0; q < 4; q++) acc[mt][nt][q] = 0.f;

#define ISSUE(c) do {                                                     \
        uint32_t off = ((c) % 3) * STAGESZ;                               \
        const char* as = Asrc + (c) * 128;                                \
        const char* bs = Bsrc + (c) * 128;                                \
        CP16(stsA + off +  0, as +  0); CP16(stsB + off +  0, bs +  0);   \
        CP16(stsA + off + 16, as + 16); CP16(stsB + off + 16, bs + 16);   \
        CP16(stsA + off + 32, as + 32); CP16(stsB + off + 32, bs + 32);   \
        CP16(stsA + off + 48, as + 48); CP16(stsB + off + 48, bs + 48);   \
        CPCOMMIT();                                                       \
    } while (0)

    ISSUE(0); ISSUE(1);
#pragma unroll 1
    for (int c = 0; c < NCH; c++) {
        if (c < NCH - 1) { CPWAIT(1); } else { CPWAIT(0); }
        __syncthreads();
        if (c + 2 < NCH) ISSUE(c + 2);
        const uint32_t off = (c % 3) * STAGESZ;
#pragma unroll
        for (int ks = 0; ks < 4; ks++) {
            const uint32_t ka = off + ks * 32;
            uint32_t af[2][4];
            ldm_x4(af[0][0], af[0][1], af[0][2], af[0][3], aAddr + ka);
            ldm_x4(af[1][0], af[1][1], af[1][2], af[1][3], aAddr + ka + 16 * PITCHB);
            uint32_t bf[8][2];
#pragma unroll
            for (int p = 0; p < 4; p++) {
                uint32_t r0, r1, r2, r3;
                ldm_x4(r0, r1, r2, r3, bAddr + ka + p * 16 * PITCHB);
                bf[2 * p][0] = r0;     bf[2 * p][1] = r1;
                bf[2 * p + 1][0] = r2; bf[2 * p + 1][1] = r3;
            }
#pragma unroll
            for (int mt = 0; mt < 2; mt++)
#pragma unroll
                for (int nt = 0; nt < 8; nt++)
                    mma_f16(acc[mt][nt], af[mt], bf[nt]);
        }
    }

    const int g = lane >> 2, tig = lane & 3;
#pragma unroll
    for (int mt = 0; mt < 2; mt++) {
#pragma unroll
        for (int nt = 0; nt < 8; nt++) {
            int col = colBase + wn + nt * 8 + tig * 2;
            float2 bb = *(const float2*)(bias + col);
            int r0 = rowBase + wm + mt * 16 + g;
            int r1 = r0 + 8;
            float2 v0 = { acc[mt][nt][0] + bb.x, acc[mt][nt][1] + bb.y };
            float2 v1 = { acc[mt][nt][2] + bb.x, acc[mt][nt][3] + bb.y };
            if (doRelu) {
                v0.x = fmaxf(v0.x, 0.f); v0.y = fmaxf(v0.y, 0.f);
                v1.x = fmaxf(v1.x, 0.f); v1.y = fmaxf(v1.y, 0.f);
            }
            if (C16) {
                if (r0 < M) *(__half2*)(C16 + (size_t)r0 * ldc + col) = __floats2half2_rn(v0.x, v0.y);
                if (r1 < M) *(__half2*)(C16 + (size_t)r1 * ldc + col) = __floats2half2_rn(v1.x, v1.y);
            } else {
                if (r0 < M) *(float2*)(C + (size_t)r0 * ldc + col) = v0;
                if (r1 < M) *(float2*)(C + (size_t)r1 * ldc + col) = v1;
            }
        }
    }
}

// ---------------- conversions / repack ----------------
__global__ void f2h_kernel(const float* __restrict__ s, __half* __restrict__ d, int n) {
    int i = (blockIdx.x * blockDim.x + threadIdx.x) * 8;
    if (i >= n) return;
    float4 a = *(const float4*)(s + i);
    float4 b = *(const float4*)(s + i + 4);
    __half2 r[4] = { __floats2half2_rn(a.x, a.y), __floats2half2_rn(a.z, a.w),
                     __floats2half2_rn(b.x, b.y), __floats2half2_rn(b.z, b.w) };
    *(float4*)(d + i) = *(float4*)r;
}

// x -> bgh16[:,256:512] (fp16, stride 512)
__global__ void x2h_strided(const float* __restrict__ x, __half* __restrict__ bgh16) {
    int n = blockIdx.x, c = threadIdx.x;
    bgh16[(size_t)n * 512 + 256 + c] = __float2half(x[(size_t)n * DD + c]);
}

// w_rz[l][o][0:256]=wih[l][o], [256:512]=whh[l][o]  (o in 0..511), fp16
__global__ void wrz_pack(const float* __restrict__ wih, const float* __restrict__ whh,
                         __half* __restrict__ wrz) {
    int idx = blockIdx.x * blockDim.x + threadIdx.x;
    if (idx >= LLAYERS * 512 * 512) return;
    int l = idx >> 18, rem = idx & 0x3FFFF;
    int o = rem >> 9, k = rem & 511;
    float v = (k < 256) ? wih[(size_t)l * 768 * 256 + o * 256 + k]
                        : whh[(size_t)l * 768 * 256 + o * 256 + (k - 256)];
    wrz[idx] = __float2half(v);
}

__global__ void brz_pack(const float* __restrict__ bih, const float* __restrict__ bhh) {
    int i = blockIdx.x * blockDim.x + threadIdx.x;
    if (i >= LLAYERS * 512) return;
    int l = i >> 9, o = i & 511;
    g_brzb[i] = bih[l * 768 + o] + bhh[l * 768 + o];
}

__global__ void vcopy4(const float4* __restrict__ src, float4* __restrict__ dst, int n4) {
    int i = blockIdx.x * blockDim.x + threadIdx.x;
    if (i < n4) dst[i] = src[i];
}

// ---------------- CSR ----------------
__global__ void csr_zero_kernel() {
    int i = blockIdx.x * blockDim.x + threadIdx.x;
    if (i < NN) g_deg[i] = 0;
}
__global__ void csr_hist_kernel(const int* __restrict__ dst) {
    int e = blockIdx.x * blockDim.x + threadIdx.x;
    if (e < EE) atomicAdd(&g_deg[dst[e]], 1);
}
__global__ void csr_scan_kernel() {
    __shared__ int warpsums[32];
    __shared__ int sbase;
    int tid = threadIdx.x;
    if (tid == 0) sbase = 0;
    __syncthreads();
    for (int start = 0; start < NN; start += 1024) {
        int i = start + tid;
        int v = (i < NN) ? g_deg[i] : 0;
        int x = v;
#pragma unroll
        for (int o = 1; o < 32; o <<= 1) {
            int t = __shfl_up_sync(~0u, x, o);
            if ((tid & 31) >= o) x += t;
        }
        if ((tid & 31) == 31) warpsums[tid >> 5] = x;
        __syncthreads();
        if (tid < 32) {
            int w = warpsums[tid];
#pragma unroll
            for (int o = 1; o < 32; o <<= 1) {
                int t = __shfl_up_sync(~0u, w, o);
                if (tid >= o) w += t;
            }
            warpsums[tid] = w;
        }
        __syncthreads();
        int ex = x - v + ((tid >= 32) ? warpsums[(tid >> 5) - 1] : 0) + sbase;
        if (i < NN) { g_off[i] = ex; g_cur[i] = ex; }
        __syncthreads();
        if (tid == 0) sbase += warpsums[31];
        __syncthreads();
    }
    if (tid == 0) g_off[NN] = sbase;
}
__global__ void csr_scatter_kernel(const int* __restrict__ src, const int* __restrict__ dst) {
    int e = blockIdx.x * blockDim.x + threadIdx.x;
    if (e >= EE) return;
    int pos = atomicAdd(&g_cur[dst[e]], 1);
    g_csr[pos] = src[e];
}

// agg16[n] = fp16( h16[n] + sum h16[j] ), fp32 accumulation; h16 strided in bgh16
__global__ __launch_bounds__(256) void gather_agg16(const __half* __restrict__ bgh16,
                                                    __half* __restrict__ agg16) {
    int n = blockIdx.x, c = threadIdx.x;
    float s = __half2float(bgh16[(size_t)n * 512 + 256 + c]);
    int beg = g_off[n], end = g_off[n + 1];
    for (int j = beg; j < end; j++) {
        int sidx = __ldg(&g_csr[j]);
        s += __half2float(bgh16[(size_t)sidx * 512 + 256 + c]);
    }
    agg16[(size_t)n * DD + c] = __float2half(s);
}

// ---------------- BatchNorm ----------------
__global__ void bn_zero_kernel() {
    int c = threadIdx.x;
    if (c < DD) { g_bnsum[c] = 0.f; g_bnsq[c] = 0.f; }
}
__global__ void bn_stats_kernel(const float* __restrict__ gbuf) {
    int c = threadIdx.x;
    int r0 = blockIdx.x * 256;
    int r1 = min(r0 + 256, NN);
    float s = 0.f, s2 = 0.f;
    for (int r = r0; r < r1; r++) {
        float v = gbuf[(size_t)r * DD + c];
        s += v; s2 += v * v;
    }
    atomicAdd(&g_bnsum[c], s);
    atomicAdd(&g_bnsq[c], s2);
}
__global__ void bn_final_kernel(const float* __restrict__ bng, const float* __restrict__ bnb) {
    int c = threadIdx.x;
    if (c >= DD) return;
    float invN = 1.f / (float)NN;
    float mean = g_bnsum[c] * invN;
    float var  = g_bnsq[c] * invN - mean * mean;
    float sc   = bng[c] * rsqrtf(var + EPS);
    g_scale[c] = sc;
    g_shift[c] = bnb[c] - mean * sc;
}
// writes normalized g into bgh16[:,0:256]
__global__ void bn_apply16_kernel(const float* __restrict__ gbuf, __half* __restrict__ bgh16) {
    int c = threadIdx.x;
    bgh16[(size_t)blockIdx.x * 512 + c] =
        __float2half(fmaf(gbuf[(size_t)blockIdx.x * DD + c], g_scale[c], g_shift[c]));
}

// ---------------- GRU gates + LayerNorm + m/e + fused segment-max ----------------
__inline__ __device__ float warpsum(float v) {
#pragma unroll
    for (int o = 16; o > 0; o >>= 1) v += __shfl_xor_sync(0xffffffffu, v, o);
    return v;
}

__global__ __launch_bounds__(256) void gru_ln_kernel(
    const float* __restrict__ rzbuf, const float* __restrict__ inbuf,
    const float* __restrict__ hnbuf,
    float* __restrict__ h, __half* __restrict__ bgh16,
    const float* __restrict__ lng, const float* __restrict__ lnb,
    float* __restrict__ m, float* __restrict__ e,
    const int* __restrict__ batch, unsigned* __restrict__ outk, int layer)
{
    int n = blockIdx.x;
    int c = threadIdx.x;

    float rz_r = rzbuf[(size_t)n * 512 + c];
    float rz_z = rzbuf[(size_t)n * 512 + 256 + c];
    float inn  = inbuf[(size_t)n * DD + c];
    float hnn  = hnbuf[(size_t)n * DD + c];
    float r  = 1.f / (1.f + expf(-rz_r));
    float z  = 1.f / (1.f + expf(-rz_z));
    float nn = tanhf(inn + r * hnn);
    float hold = h[(size_t)n * DD + c];
    float hv = (1.f - z) * nn + z * hold;

    __shared__ float sbuf[8];
    int lane = c & 31, w = c >> 5;
    float s = warpsum(hv);
    if (lane == 0) sbuf[w] = s;
    __syncthreads();
    float mu = 0.f;
#pragma unroll
    for (int i = 0; i < 8; i++) mu += sbuf[i];
    mu *= (1.f / 256.f);
    __syncthreads();
    float d0 = hv - mu;
    float s2 = warpsum(d0 * d0);
    if (lane == 0) sbuf[w] = s2;
    __syncthreads();
    float var = 0.f;
#pragma unroll
    for (int i = 0; i < 8; i++) var += sbuf[i];
    var *= (1.f / 256.f);

    float o = d0 * rsqrtf(var + EPS) * lng[c] + lnb[c];

    size_t idx = (size_t)n * DD + c;
    h[idx] = o;
    bgh16[(size_t)n * 512 + 256 + c] = __float2half(o);
    float mv, ev;
    if (layer == 0) { mv = o; ev = o; }
    else            { mv = m[idx] * o; ev = e[idx] + o; }
    m[idx] = mv; e[idx] = ev;

    int b = __ldg(&batch[n]);
    unsigned* orow = outk + (size_t)b * OUTW;
    atomicMax(&orow[layer * DD + c], fkey(o));
    if (layer == LLAYERS - 1) {
        atomicMax(&orow[3 * DD + c], fkey(mv));
        atomicMax(&orow[4 * DD + c], fkey(ev));
    }
}

__global__ void out_init_kernel(unsigned* __restrict__ outk) {
    int i = blockIdx.x * blockDim.x + threadIdx.x;
    if (i < GG * OUTW) outk[i] = 0x007FFFFFu;
}
__global__ void out_finish_kernel(unsigned* __restrict__ outk) {
    int i = blockIdx.x * blockDim.x + threadIdx.x;
    if (i >= GG * OUTW) return;
    unsigned u = outk[i];
    outk[i] = (u & 0x80000000u) ? (u ^ 0x80000000u) : ~u;
}

// ---------------- launch ----------------
extern "C" void kernel_launch(void* const* d_in, const int* in_sizes, int n_in,
                              void* d_out, int out_size) {
    const float* x       = (const float*)d_in[0];
    const float* lin1_w  = (const float*)d_in[1];
    const float* lin1_b  = (const float*)d_in[2];
    const float* lin2_w  = (const float*)d_in[3];
    const float* lin2_b  = (const float*)d_in[4];
    const float* bn_g    = (const float*)d_in[5];
    const float* bn_b    = (const float*)d_in[6];
    const float* gru_wih = (const float*)d_in[7];
    const float* gru_whh = (const float*)d_in[8];
    const float* gru_bih = (const float*)d_in[9];
    const float* gru_bhh = (const float*)d_in[10];
    const float* ln_g    = (const float*)d_in[11];
    const float* ln_b    = (const float*)d_in[12];
    const int*   edges   = (const int*)d_in[13];
    const int*   batch   = (const int*)d_in[14];
    unsigned* outk = (unsigned*)d_out;

    float* S = nullptr;
    cudaGetSymbolAddress((void**)&S, g_scratch);
    __half* W16 = nullptr;
    cudaGetSymbolAddress((void**)&W16, g_w16);
    float* brzb = nullptr;
    cudaGetSymbolAddress((void**)&brzb, g_brzb);

    const size_t ND = (size_t)NN * DD;
    float* bh   = S;
    float* bg   = S + 1 * ND;
    float* bm   = S + 2 * ND;
    float* be   = S + 3 * ND;
    float* brz  = S + 4 * ND;        // [N,512]
    float* bin  = S + 6 * ND;
    float* bhn  = S + 7 * ND;
    __half* bagg16 = (__half*)(S + 8 * ND);
    __half* bt1_16 = bagg16 + ND;
    __half* bgh16  = (__half*)(S + 9 * ND);   // [N,512] fp16

    const size_t WD = (size_t)DD * DD;        // 65536
    __half* w1_16  = W16;                      // 3*WD
    __half* w2_16  = W16 + 3 * WD;             // 3*WD
    __half* wih16  = W16 + 6 * WD;             // 9*WD (full, n-rows used)
    __half* whh16  = W16 + 15 * WD;            // 9*WD
    __half* wrz16  = W16 + 24 * WD;            // 3*4*WD = 12*WD  (total 36*WD = 2359296)

    static int smem_set = 0;
    if (!smem_set) {
        cudaFuncSetAttribute(gemm16, cudaFuncAttributeMaxDynamicSharedMemorySize, SMEM_DYN);
        smem_set = 1;
    }

    const int n4 = (int)(ND / 4);
    const int MT = (NN + 127) / 128;
    const dim3 grid_d(2, MT);    // O=256
    const dim3 grid_rz(4, MT);   // O=512

    // one-time conversions + packs
    {
        int nw = LLAYERS * (int)WD;
        f2h_kernel<<<(nw / 8 + 255) / 256, 256>>>(lin1_w, w1_16, nw);
        f2h_kernel<<<(nw / 8 + 255) / 256, 256>>>(lin2_w, w2_16, nw);
        int nw3 = 3 * nw;
        f2h_kernel<<<(nw3 / 8 + 255) / 256, 256>>>(gru_wih, wih16, nw3);
        f2h_kernel<<<(nw3 / 8 + 255) / 256, 256>>>(gru_whh, whh16, nw3);
        wrz_pack<<<(LLAYERS * 512 * 512 + 255) / 256, 256>>>(gru_wih, gru_whh, wrz16);
        brz_pack<<<(LLAYERS * 512 + 255) / 256, 256>>>(gru_bih, gru_bhh);
    }
    vcopy4<<<(n4 + 255) / 256, 256>>>((const float4*)x, (float4*)bh, n4);
    x2h_strided<<<NN, 256>>>(x, bgh16);
    out_init_kernel<<<(GG * OUTW + 255) / 256, 256>>>(outk);

    // CSR build
    csr_zero_kernel<<<(NN + 255) / 256, 256>>>();
    csr_hist_kernel<<<(EE + 255) / 256, 256>>>(edges + EE);
    csr_scan_kernel<<<1, 1024>>>();
    csr_scatter_kernel<<<(EE + 255) / 256, 256>>>(edges, edges + EE);

    for (int i = 0; i < LLAYERS; i++) {
        gather_agg16<<<NN, 256>>>(bgh16, bagg16);

        // GIN MLP
        gemm16<<<grid_d, 256, SMEM_DYN>>>(bagg16, 256, w1_16 + i * WD,
                                          lin1_b + (size_t)i * DD, nullptr, bt1_16, 256,
                                          NN, 256, 1);
        gemm16<<<grid_d, 256, SMEM_DYN>>>(bt1_16, 256, w2_16 + i * WD,
                                          lin2_b + (size_t)i * DD, bg, nullptr, 256,
                                          NN, 256, 1);

        // BatchNorm -> bgh16[:,0:256]
        bn_zero_kernel<<<1, 256>>>();
        bn_stats_kernel<<<(NN + 255) / 256, 256>>>(bg);
        bn_final_kernel<<<1, 256>>>(bn_g + (size_t)i * DD, bn_b + (size_t)i * DD);
        bn_apply16_kernel<<<NN, 256>>>(bg, bgh16);

        // fused r/z: [g16|h16] @ [Wih_rz|Whh_rz]^T  (K=512, O=512)
        gemm16<<<grid_rz, 256, SMEM_DYN>>>(bgh16, 512, wrz16 + (size_t)i * 512 * 512,
                                           brzb + i * 512, brz, nullptr, 512,
                                           NN, 512, 0);
        // i_n = g16 @ Wih_n^T ; h_n = h16 @ Whh_n^T
        gemm16<<<grid_d, 256, SMEM_DYN>>>(bgh16, 512, wih16 + (size_t)i * 3 * WD + 2 * WD,
                                          gru_bih + (size_t)i * 768 + 512, bin, nullptr, 256,
                                          NN, 256, 0);
        gemm16<<<grid_d, 256, SMEM_DYN>>>(bgh16 + 256, 512, whh16 + (size_t)i * 3 * WD + 2 * WD,
                                          gru_bhh + (size_t)i * 768 + 512, bhn, nullptr, 256,
                                          NN, 256, 0);

        gru_ln_kernel<<<NN, 256>>>(brz, bin, bhn, bh, bgh16, ln_g, ln_b, bm, be,
                                   batch, outk, i);
    }

    out_finish_kernel<<<(GG * OUTW + 255) / 256, 256>>>(outk);
}

// round 12
// speedup vs baseline: 2.9628x; 1.0363x over previous
#include <cuda_runtime.h>
#include <cuda_fp16.h>
#include <cstdint>
#include <math.h>

#define NN 100000
#define DD 256
#define EE 320000
#define GG 4096
#define LLAYERS 3
#define OUTW 1280
#define EPS 1e-5f

// ---------------- scratch (device globals; no allocation) ----------------
// fp32 slots: bh 0, bm 1, be 2, bin 3, bhn 4; fp16: slot5 = agg16|t1_16,
// slot6 = bgh16 [N,512], slot7(lo) = bg16pre, slot8 = brz16 [N,512]
__device__ float g_scratch[9ULL * NN * DD];
__device__ __half g_w16[2400000];
__device__ float g_brzb[LLAYERS * 512];
__device__ float g_bnsum[DD];
__device__ float g_bnsq[DD];
__device__ float g_scale[DD];
__device__ float g_shift[DD];
// CSR
__device__ int g_deg[NN];
__device__ int g_off[NN + 1];
__device__ int g_cur[NN];
__device__ int g_csr[EE];

// ---------------- helpers ----------------
__device__ __forceinline__ uint32_t smem_u32(const void* p) {
    uint32_t a;
    asm("{ .reg .u64 t; cvta.to.shared.u64 t, %1; cvt.u32.u64 %0, t; }" : "=r"(a) : "l"(p));
    return a;
}
__device__ __forceinline__ void ldm_x4(uint32_t& r0, uint32_t& r1, uint32_t& r2, uint32_t& r3,
                                       uint32_t addr) {
    asm volatile("ldmatrix.sync.aligned.m8n8.x4.shared.b16 {%0,%1,%2,%3}, [%4];"
                 : "=r"(r0), "=r"(r1), "=r"(r2), "=r"(r3) : "r"(addr));
}
__device__ __forceinline__ void mma_f16(float* d, const uint32_t* a, const uint32_t* b) {
    asm volatile("mma.sync.aligned.m16n8k16.row.col.f32.f16.f16.f32 "
                 "{%0,%1,%2,%3}, {%4,%5,%6,%7}, {%8,%9}, {%0,%1,%2,%3};"
                 : "+f"(d[0]), "+f"(d[1]), "+f"(d[2]), "+f"(d[3])
                 : "r"(a[0]), "r"(a[1]), "r"(a[2]), "r"(a[3]), "r"(b[0]), "r"(b[1]));
}
#define CP16(dst, src) asm volatile("cp.async.cg.shared.global [%0], [%1], 16;" :: "r"(dst), "l"(src))
#define CPCOMMIT()     asm volatile("cp.async.commit_group;")
#define CPWAIT(n)      asm volatile("cp.async.wait_group %0;" :: "n"(n))

__device__ __forceinline__ unsigned fkey(float f) {
    unsigned u = __float_as_uint(f);
    return (u & 0x80000000u) ? ~u : (u | 0x80000000u);
}

#define PITCHB 144
#define BUFSZ 18432
#define STAGESZ 36864
#define SMEM_DYN 110592

// ---------------- fp16 mma GEMM: C[M,O] = A[M,K](lda) @ W[O,K]^T + bias ----------------
__global__ __launch_bounds__(256, 2) void gemm16(
    const __half* __restrict__ A, int lda, const __half* __restrict__ W,
    const float* __restrict__ bias, float* __restrict__ C, __half* __restrict__ C16,
    int ldc, int M, int K, int doRelu)
{
    extern __shared__ char smem[];
    const uint32_t sb = smem_u32(smem);
    const int tid = threadIdx.x, lane = tid & 31, wid = tid >> 5;
    const int rowBase = blockIdx.y * 128, colBase = blockIdx.x * 128;
    const int wm = (wid & 3) * 32, wn = (wid >> 2) * 64;
    const int NCH = K >> 6;

    const int srow = tid >> 1, shalf = tid & 1;
    const char* Asrc = (const char*)(A + (size_t)min(rowBase + srow, M - 1) * lda) + shalf * 64;
    const char* Bsrc = (const char*)(W + (size_t)(colBase + srow) * K) + shalf * 64;
    const uint32_t stsA = sb + srow * PITCHB + shalf * 64;
    const uint32_t stsB = stsA + BUFSZ;

    const uint32_t aAddr = sb + (wm + (lane & 7) + ((lane >> 3) & 1) * 8) * PITCHB + (lane >> 4) * 16;
    const uint32_t bAddr = sb + BUFSZ + (wn + (lane & 7) + (lane >> 4) * 8) * PITCHB + ((lane >> 3) & 1) * 16;

    float acc[2][8][4];
#pragma unroll
    for (int mt = 0; mt < 2; mt++)
#pragma unroll
        for (int nt = 0; nt < 8; nt++)
#pragma unroll
            for (int q = 0; q < 4; q++) acc[mt][nt][q] = 0.f;

#define ISSUE(c) do {                                                     \
        uint32_t off = ((c) % 3) * STAGESZ;                               \
        const char* as = Asrc + (c) * 128;                                \
        const char* bs = Bsrc + (c) * 128;                                \
        CP16(stsA + off +  0, as +  0); CP16(stsB + off +  0, bs +  0);   \
        CP16(stsA + off + 16, as + 16); CP16(stsB + off + 16, bs + 16);   \
        CP16(stsA + off + 32, as + 32); CP16(stsB + off + 32, bs + 32);   \
        CP16(stsA + off + 48, as + 48); CP16(stsB + off + 48, bs + 48);   \
        CPCOMMIT();                                                       \
    } while (0)

    ISSUE(0); ISSUE(1);
#pragma unroll 1
    for (int c = 0; c < NCH; c++) {
        if (c < NCH - 1) { CPWAIT(1); } else { CPWAIT(0); }
        __syncthreads();
        if (c + 2 < NCH) ISSUE(c + 2);
        const uint32_t off = (c % 3) * STAGESZ;
#pragma unroll
        for (int ks = 0; ks < 4; ks++) {
            const uint32_t ka = off + ks * 32;
            uint32_t af[2][4];
            ldm_x4(af[0][0], af[0][1], af[0][2], af[0][3], aAddr + ka);
            ldm_x4(af[1][0], af[1][1], af[1][2], af[1][3], aAddr + ka + 16 * PITCHB);
            uint32_t bf[8][2];
#pragma unroll
            for (int p = 0; p < 4; p++) {
                uint32_t r0, r1, r2, r3;
                ldm_x4(r0, r1, r2, r3, bAddr + ka + p * 16 * PITCHB);
                bf[2 * p][0] = r0;     bf[2 * p][1] = r1;
                bf[2 * p + 1][0] = r2; bf[2 * p + 1][1] = r3;
            }
#pragma unroll
            for (int mt = 0; mt < 2; mt++)
#pragma unroll
                for (int nt = 0; nt < 8; nt++)
                    mma_f16(acc[mt][nt], af[mt], bf[nt]);
        }
    }

    const int g = lane >> 2, tig = lane & 3;
#pragma unroll
    for (int mt = 0; mt < 2; mt++) {
#pragma unroll
        for (int nt = 0; nt < 8; nt++) {
            int col = colBase + wn + nt * 8 + tig * 2;
            float2 bb = *(const float2*)(bias + col);
            int r0 = rowBase + wm + mt * 16 + g;
            int r1 = r0 + 8;
            float2 v0 = { acc[mt][nt][0] + bb.x, acc[mt][nt][1] + bb.y };
            float2 v1 = { acc[mt][nt][2] + bb.x, acc[mt][nt][3] + bb.y };
            if (doRelu) {
                v0.x = fmaxf(v0.x, 0.f); v0.y = fmaxf(v0.y, 0.f);
                v1.x = fmaxf(v1.x, 0.f); v1.y = fmaxf(v1.y, 0.f);
            }
            if (C16) {
                if (r0 < M) *(__half2*)(C16 + (size_t)r0 * ldc + col) = __floats2half2_rn(v0.x, v0.y);
                if (r1 < M) *(__half2*)(C16 + (size_t)r1 * ldc + col) = __floats2half2_rn(v1.x, v1.y);
            } else {
                if (r0 < M) *(float2*)(C + (size_t)r0 * ldc + col) = v0;
                if (r1 < M) *(float2*)(C + (size_t)r1 * ldc + col) = v1;
            }
        }
    }
}

// ---------------- conversions / repack ----------------
__global__ void f2h_kernel(const float* __restrict__ s, __half* __restrict__ d, int n) {
    int i = (blockIdx.x * blockDim.x + threadIdx.x) * 8;
    if (i >= n) return;
    float4 a = *(const float4*)(s + i);
    float4 b = *(const float4*)(s + i + 4);
    __half2 r[4] = { __floats2half2_rn(a.x, a.y), __floats2half2_rn(a.z, a.w),
                     __floats2half2_rn(b.x, b.y), __floats2half2_rn(b.z, b.w) };
    *(float4*)(d + i) = *(float4*)r;
}

__global__ void x2h_strided(const float* __restrict__ x, __half* __restrict__ bgh16) {
    int n = blockIdx.x, c = threadIdx.x;
    bgh16[(size_t)n * 512 + 256 + c] = __float2half(x[(size_t)n * DD + c]);
}

__global__ void wrz_pack(const float* __restrict__ wih, const float* __restrict__ whh,
                         __half* __restrict__ wrz) {
    int idx = blockIdx.x * blockDim.x + threadIdx.x;
    if (idx >= LLAYERS * 512 * 512) return;
    int l = idx >> 18, rem = idx & 0x3FFFF;
    int o = rem >> 9, k = rem & 511;
    float v = (k < 256) ? wih[(size_t)l * 768 * 256 + o * 256 + k]
                        : whh[(size_t)l * 768 * 256 + o * 256 + (k - 256)];
    wrz[idx] = __float2half(v);
}

__global__ void brz_pack(const float* __restrict__ bih, const float* __restrict__ bhh) {
    int i = blockIdx.x * blockDim.x + threadIdx.x;
    if (i >= LLAYERS * 512) return;
    int l = i >> 9, o = i & 511;
    g_brzb[i] = bih[l * 768 + o] + bhh[l * 768 + o];
}

__global__ void vcopy4(const float4* __restrict__ src, float4* __restrict__ dst, int n4) {
    int i = blockIdx.x * blockDim.x + threadIdx.x;
    if (i < n4) dst[i] = src[i];
}

// ---------------- CSR ----------------
__global__ void csr_zero_kernel() {
    int i = blockIdx.x * blockDim.x + threadIdx.x;
    if (i < NN) g_deg[i] = 0;
}
__global__ void csr_hist_kernel(const int* __restrict__ dst) {
    int e = blockIdx.x * blockDim.x + threadIdx.x;
    if (e < EE) atomicAdd(&g_deg[dst[e]], 1);
}
__global__ void csr_scan_kernel() {
    __shared__ int warpsums[32];
    __shared__ int sbase;
    int tid = threadIdx.x;
    if (tid == 0) sbase = 0;
    __syncthreads();
    for (int start = 0; start < NN; start += 1024) {
        int i = start + tid;
        int v = (i < NN) ? g_deg[i] : 0;
        int x = v;
#pragma unroll
        for (int o = 1; o < 32; o <<= 1) {
            int t = __shfl_up_sync(~0u, x, o);
            if ((tid & 31) >= o) x += t;
        }
        if ((tid & 31) == 31) warpsums[tid >> 5] = x;
        __syncthreads();
        if (tid < 32) {
            int w = warpsums[tid];
#pragma unroll
            for (int o = 1; o < 32; o <<= 1) {
                int t = __shfl_up_sync(~0u, w, o);
                if (tid >= o) w += t;
            }
            warpsums[tid] = w;
        }
        __syncthreads();
        int ex = x - v + ((tid >= 32) ? warpsums[(tid >> 5) - 1] : 0) + sbase;
        if (i < NN) { g_off[i] = ex; g_cur[i] = ex; }
        __syncthreads();
        if (tid == 0) sbase += warpsums[31];
        __syncthreads();
    }
    if (tid == 0) g_off[NN] = sbase;
}
__global__ void csr_scatter_kernel(const int* __restrict__ src, const int* __restrict__ dst) {
    int e = blockIdx.x * blockDim.x + threadIdx.x;
    if (e >= EE) return;
    int pos = atomicAdd(&g_cur[dst[e]], 1);
    g_csr[pos] = src[e];
}

// agg16[n] = fp16( h16[n] + sum h16[j] ), fp32 accumulation
__global__ __launch_bounds__(256) void gather_agg16(const __half* __restrict__ bgh16,
                                                    __half* __restrict__ agg16) {
    int n = blockIdx.x, c = threadIdx.x;
    float s = __half2float(bgh16[(size_t)n * 512 + 256 + c]);
    int beg = g_off[n], end = g_off[n + 1];
    for (int j = beg; j < end; j++) {
        int sidx = __ldg(&g_csr[j]);
        s += __half2float(bgh16[(size_t)sidx * 512 + 256 + c]);
    }
    agg16[(size_t)n * DD + c] = __float2half(s);
}

// ---------------- BatchNorm (fp16 input, fp32 accumulation) ----------------
__global__ void bn_zero_kernel() {
    int c = threadIdx.x;
    if (c < DD) { g_bnsum[c] = 0.f; g_bnsq[c] = 0.f; }
}
__global__ void bn_stats16_kernel(const __half* __restrict__ g16) {
    int c = threadIdx.x;
    int r0 = blockIdx.x * 256;
    int r1 = min(r0 + 256, NN);
    float s = 0.f, s2 = 0.f;
    for (int r = r0; r < r1; r++) {
        float v = __half2float(g16[(size_t)r * DD + c]);
        s += v; s2 += v * v;
    }
    atomicAdd(&g_bnsum[c], s);
    atomicAdd(&g_bnsq[c], s2);
}
__global__ void bn_final_kernel(const float* __restrict__ bng, const float* __restrict__ bnb) {
    int c = threadIdx.x;
    if (c >= DD) return;
    float invN = 1.f / (float)NN;
    float mean = g_bnsum[c] * invN;
    float var  = g_bnsq[c] * invN - mean * mean;
    float sc   = bng[c] * rsqrtf(var + EPS);
    g_scale[c] = sc;
    g_shift[c] = bnb[c] - mean * sc;
}
// normalized g -> bgh16[:,0:256]
__global__ void bn_apply16_kernel(const __half* __restrict__ g16, __half* __restrict__ bgh16) {
    int c = threadIdx.x;
    float v = __half2float(g16[(size_t)blockIdx.x * DD + c]);
    bgh16[(size_t)blockIdx.x * 512 + c] = __float2half(fmaf(v, g_scale[c], g_shift[c]));
}

// ---------------- GRU gates + LayerNorm + m/e + fused segment-max ----------------
__inline__ __device__ float warpsum(float v) {
#pragma unroll
    for (int o = 16; o > 0; o >>= 1) v += __shfl_xor_sync(0xffffffffu, v, o);
    return v;
}

__global__ __launch_bounds__(256) void gru_ln_kernel(
    const __half* __restrict__ rz16, const float* __restrict__ inbuf,
    const float* __restrict__ hnbuf,
    float* __restrict__ h, __half* __restrict__ bgh16,
    const float* __restrict__ lng, const float* __restrict__ lnb,
    float* __restrict__ m, float* __restrict__ e,
    const int* __restrict__ batch, unsigned* __restrict__ outk, int layer)
{
    int n = blockIdx.x;
    int c = threadIdx.x;

    float rz_r = __half2float(rz16[(size_t)n * 512 + c]);
    float rz_z = __half2float(rz16[(size_t)n * 512 + 256 + c]);
    float inn  = inbuf[(size_t)n * DD + c];
    float hnn  = hnbuf[(size_t)n * DD + c];
    float r  = 1.f / (1.f + expf(-rz_r));
    float z  = 1.f / (1.f + expf(-rz_z));
    float nn = tanhf(inn + r * hnn);
    float hold = h[(size_t)n * DD + c];
    float hv = (1.f - z) * nn + z * hold;

    __shared__ float sbuf[8];
    int lane = c & 31, w = c >> 5;
    float s = warpsum(hv);
    if (lane == 0) sbuf[w] = s;
    __syncthreads();
    float mu = 0.f;
#pragma unroll
    for (int i = 0; i < 8; i++) mu += sbuf[i];
    mu *= (1.f / 256.f);
    __syncthreads();
    float d0 = hv - mu;
    float s2 = warpsum(d0 * d0);
    if (lane == 0) sbuf[w] = s2;
    __syncthreads();
    float var = 0.f;
#pragma unroll
    for (int i = 0; i < 8; i++) var += sbuf[i];
    var *= (1.f / 256.f);

    float o = d0 * rsqrtf(var + EPS) * lng[c] + lnb[c];

    size_t idx = (size_t)n * DD + c;
    h[idx] = o;
    bgh16[(size_t)n * 512 + 256 + c] = __float2half(o);
    float mv, ev;
    if (layer == 0) { mv = o; ev = o; }
    else            { mv = m[idx] * o; ev = e[idx] + o; }
    m[idx] = mv; e[idx] = ev;

    int b = __ldg(&batch[n]);
    unsigned* orow = outk + (size_t)b * OUTW;
    atomicMax(&orow[layer * DD + c], fkey(o));
    if (layer == LLAYERS - 1) {
        atomicMax(&orow[3 * DD + c], fkey(mv));
        atomicMax(&orow[4 * DD + c], fkey(ev));
    }
}

__global__ void out_init_kernel(unsigned* __restrict__ outk) {
    int i = blockIdx.x * blockDim.x + threadIdx.x;
    if (i < GG * OUTW) outk[i] = 0x007FFFFFu;
}
__global__ void out_finish_kernel(unsigned* __restrict__ outk) {
    int i = blockIdx.x * blockDim.x + threadIdx.x;
    if (i >= GG * OUTW) return;
    unsigned u = outk[i];
    outk[i] = (u & 0x80000000u) ? (u ^ 0x80000000u) : ~u;
}

// ---------------- launch ----------------
extern "C" void kernel_launch(void* const* d_in, const int* in_sizes, int n_in,
                              void* d_out, int out_size) {
    const float* x       = (const float*)d_in[0];
    const float* lin1_w  = (const float*)d_in[1];
    const float* lin1_b  = (const float*)d_in[2];
    const float* lin2_w  = (const float*)d_in[3];
    const float* lin2_b  = (const float*)d_in[4];
    const float* bn_g    = (const float*)d_in[5];
    const float* bn_b    = (const float*)d_in[6];
    const float* gru_wih = (const float*)d_in[7];
    const float* gru_whh = (const float*)d_in[8];
    const float* gru_bih = (const float*)d_in[9];
    const float* gru_bhh = (const float*)d_in[10];
    const float* ln_g    = (const float*)d_in[11];
    const float* ln_b    = (const float*)d_in[12];
    const int*   edges   = (const int*)d_in[13];
    const int*   batch   = (const int*)d_in[14];
    unsigned* outk = (unsigned*)d_out;

    float* S = nullptr;
    cudaGetSymbolAddress((void**)&S, g_scratch);
    __half* W16 = nullptr;
    cudaGetSymbolAddress((void**)&W16, g_w16);
    float* brzb = nullptr;
    cudaGetSymbolAddress((void**)&brzb, g_brzb);

    const size_t ND = (size_t)NN * DD;
    float* bh   = S;
    float* bm   = S + 1 * ND;
    float* be   = S + 2 * ND;
    float* bin  = S + 3 * ND;
    float* bhn  = S + 4 * ND;
    __half* bagg16  = (__half*)(S + 5 * ND);        // ND halfs
    __half* bt1_16  = bagg16 + ND;                  // ND halfs
    __half* bgh16   = (__half*)(S + 6 * ND);        // [N,512] halfs
    __half* bg16pre = (__half*)(S + 7 * ND);        // ND halfs
    __half* brz16   = (__half*)(S + 8 * ND);        // [N,512] halfs

    const size_t WD = (size_t)DD * DD;
    __half* w1_16 = W16;
    __half* w2_16 = W16 + 3 * WD;
    __half* wih16 = W16 + 6 * WD;
    __half* whh16 = W16 + 15 * WD;
    __half* wrz16 = W16 + 24 * WD;

    static int smem_set = 0;
    if (!smem_set) {
        cudaFuncSetAttribute(gemm16, cudaFuncAttributeMaxDynamicSharedMemorySize, SMEM_DYN);
        smem_set = 1;
    }

    const int n4 = (int)(ND / 4);
    const int MT = (NN + 127) / 128;
    const dim3 grid_d(2, MT);    // O=256
    const dim3 grid_rz(4, MT);   // O=512

    {
        int nw = LLAYERS * (int)WD;
        f2h_kernel<<<(nw / 8 + 255) / 256, 256>>>(lin1_w, w1_16, nw);
        f2h_kernel<<<(nw / 8 + 255) / 256, 256>>>(lin2_w, w2_16, nw);
        int nw3 = 3 * nw;
        f2h_kernel<<<(nw3 / 8 + 255) / 256, 256>>>(gru_wih, wih16, nw3);
        f2h_kernel<<<(nw3 / 8 + 255) / 256, 256>>>(gru_whh, whh16, nw3);
        wrz_pack<<<(LLAYERS * 512 * 512 + 255) / 256, 256>>>(gru_wih, gru_whh, wrz16);
        brz_pack<<<(LLAYERS * 512 + 255) / 256, 256>>>(gru_bih, gru_bhh);
    }
    vcopy4<<<(n4 + 255) / 256, 256>>>((const float4*)x, (float4*)bh, n4);
    x2h_strided<<<NN, 256>>>(x, bgh16);
    out_init_kernel<<<(GG * OUTW + 255) / 256, 256>>>(outk);

    csr_zero_kernel<<<(NN + 255) / 256, 256>>>();
    csr_hist_kernel<<<(EE + 255) / 256, 256>>>(edges + EE);
    csr_scan_kernel<<<1, 1024>>>();
    csr_scatter_kernel<<<(EE + 255) / 256, 256>>>(edges, edges + EE);

    for (int i = 0; i < LLAYERS; i++) {
        gather_agg16<<<NN, 256>>>(bgh16, bagg16);

        // GIN MLP (both fp16 outputs now)
        gemm16<<<grid_d, 256, SMEM_DYN>>>(bagg16, 256, w1_16 + i * WD,
                                          lin1_b + (size_t)i * DD, nullptr, bt1_16, 256,
                                          NN, 256, 1);
        gemm16<<<grid_d, 256, SMEM_DYN>>>(bt1_16, 256, w2_16 + i * WD,
                                          lin2_b + (size_t)i * DD, nullptr, bg16pre, 256,
                                          NN, 256, 1);

        // BatchNorm from fp16 pre-activation -> bgh16[:,0:256]
        bn_zero_kernel<<<1, 256>>>();
        bn_stats16_kernel<<<(NN + 255) / 256, 256>>>(bg16pre);
        bn_final_kernel<<<1, 256>>>(bn_g + (size_t)i * DD, bn_b + (size_t)i * DD);
        bn_apply16_kernel<<<NN, 256>>>(bg16pre, bgh16);

        // fused r/z (fp16 output)
        gemm16<<<grid_rz, 256, SMEM_DYN>>>(bgh16, 512, wrz16 + (size_t)i * 512 * 512,
                                           brzb + i * 512, nullptr, brz16, 512,
                                           NN, 512, 0);
        // i_n / h_n stay fp32
        gemm16<<<grid_d, 256, SMEM_DYN>>>(bgh16, 512, wih16 + (size_t)i * 3 * WD + 2 * WD,
                                          gru_bih + (size_t)i * 768 + 512, bin, nullptr, 256,
                                          NN, 256, 0);
        gemm16<<<grid_d, 256, SMEM_DYN>>>(bgh16 + 256, 512, whh16 + (size_t)i * 3 * WD + 2 * WD,
                                          gru_bhh + (size_t)i * 768 + 512, bhn, nullptr, 256,
                                          NN, 256, 0);

        gru_ln_kernel<<<NN, 256>>>(brz16, bin, bhn, bh, bgh16, ln_g, ln_b, bm, be,
                                   batch, outk, i);
    }

    out_finish_kernel<<<(GG * OUTW + 255) / 256, 256>>>(outk);
}